// round 1
// baseline (speedup 1.0000x reference)
#include <cuda_runtime.h>
#include <math.h>

// Problem constants
#define NWIN 64
#define NTOK 512
#define NHEAD 8
#define HDIM 32
#define CDIM 256

// Scratch (device globals -- no allocation allowed)
__device__ float g_q[NWIN * NHEAD * NTOK * HDIM];     // 33.5 MB
__device__ float g_k[NWIN * NHEAD * NTOK * HDIM];     // 33.5 MB
__device__ float g_v[NWIN * NHEAD * NTOK * HDIM];     // 33.5 MB
__device__ float g_biasT[NHEAD * NTOK * NTOK];        // 8.4 MB, biasT[h][j][i]
__device__ float g_att[NWIN * NTOK * CDIM];           // 33.5 MB, token-major
__device__ float g_sc[(size_t)NWIN * NHEAD * NTOK * NTOK]; // 537 MB score scratch
__device__ int   g_tokoff[NWIN * NTOK];               // token -> x/out element offset

// ---------------------------------------------------------------------------
// Prep: relative-position bias table (transposed) + token offset table.
// biasT[h][j][i] = rpb[idx(i,j)*8 + h], idx = (di0)*225 + (di1)*15 + di2.
// tokoff[t]: cyclic shift roll(-4) gather == roll(+4) scatter (same map).
// ---------------------------------------------------------------------------
__global__ void prep_kernel(const float* __restrict__ rpb) {
    int j = blockIdx.x;          // 0..511
    int tid = threadIdx.x;       // 0..255
    int j0 = j >> 6, j1 = (j >> 3) & 7, j2 = j & 7;
#pragma unroll
    for (int t = 0; t < 2; t++) {
        int i = tid + t * 256;
        int i0 = i >> 6, i1 = (i >> 3) & 7, i2 = i & 7;
        int idx = (i0 - j0 + 7) * 225 + (i1 - j1 + 7) * 15 + (i2 - j2 + 7);
        const float4* r = (const float4*)(rpb + idx * 8);
        float4 ra = r[0], rb = r[1];
        float vals[8] = {ra.x, ra.y, ra.z, ra.w, rb.x, rb.y, rb.z, rb.w};
#pragma unroll
        for (int hh = 0; hh < 8; hh++)
            g_biasT[((size_t)hh * 512 + j) * 512 + i] = vals[hh];
    }
    int gid = j * 256 + tid;
    if (gid < NWIN * NTOK) {
        int w = gid >> 9, n = gid & 511;
        int wh = w >> 4, ww = (w >> 2) & 3, wd = w & 3;
        int ih = n >> 6, iw = (n >> 3) & 7, id = n & 7;
        int gh = (wh * 8 + ih + 4) & 31;
        int gw = (ww * 8 + iw + 4) & 31;
        int gd = (wd * 8 + id + 4) & 31;
        g_tokoff[gid] = ((gh * 32 + gw) * 32 + gd) * 256;
    }
}

// ---------------------------------------------------------------------------
// QKV GEMM: y[t][o] = sum_c x_shifted[t][c] * W[o][c] + b[o]
// M=32768 (gathered via tokoff), N=768, K=256. Tile 64x64x16, 4x4/thread.
// Epilogue scatters into g_q/g_k/g_v in [win][head][tok][hd] layout (q scaled).
// ---------------------------------------------------------------------------
__global__ void qkv_gemm_kernel(const float* __restrict__ x,
                                const float* __restrict__ W,
                                const float* __restrict__ bias) {
    __shared__ float As[16 * 68];
    __shared__ float Bs[16 * 68];
    int tid = threadIdx.x;
    int m0 = blockIdx.x * 64, o0 = blockIdx.y * 64;
    int lr = tid >> 2, lc = (tid & 3) * 4;
    const float* aptr = x + g_tokoff[m0 + lr] + lc;
    const float* bptr = W + (size_t)(o0 + lr) * 256 + lc;
    int tx = tid & 15, ty = tid >> 4;
    float acc[4][4];
#pragma unroll
    for (int a = 0; a < 4; a++)
#pragma unroll
        for (int b = 0; b < 4; b++) acc[a][b] = 0.f;

    for (int k0 = 0; k0 < 256; k0 += 16) {
        float4 av = *(const float4*)(aptr + k0);
        float4 bv = *(const float4*)(bptr + k0);
        __syncthreads();
        As[(lc + 0) * 68 + lr] = av.x; As[(lc + 1) * 68 + lr] = av.y;
        As[(lc + 2) * 68 + lr] = av.z; As[(lc + 3) * 68 + lr] = av.w;
        Bs[(lc + 0) * 68 + lr] = bv.x; Bs[(lc + 1) * 68 + lr] = bv.y;
        Bs[(lc + 2) * 68 + lr] = bv.z; Bs[(lc + 3) * 68 + lr] = bv.w;
        __syncthreads();
#pragma unroll
        for (int kk = 0; kk < 16; kk++) {
            float4 a4 = *(const float4*)&As[kk * 68 + ty * 4];
            float4 b4 = *(const float4*)&Bs[kk * 68 + tx * 4];
            acc[0][0] = fmaf(a4.x, b4.x, acc[0][0]); acc[0][1] = fmaf(a4.x, b4.y, acc[0][1]);
            acc[0][2] = fmaf(a4.x, b4.z, acc[0][2]); acc[0][3] = fmaf(a4.x, b4.w, acc[0][3]);
            acc[1][0] = fmaf(a4.y, b4.x, acc[1][0]); acc[1][1] = fmaf(a4.y, b4.y, acc[1][1]);
            acc[1][2] = fmaf(a4.y, b4.z, acc[1][2]); acc[1][3] = fmaf(a4.y, b4.w, acc[1][3]);
            acc[2][0] = fmaf(a4.z, b4.x, acc[2][0]); acc[2][1] = fmaf(a4.z, b4.y, acc[2][1]);
            acc[2][2] = fmaf(a4.z, b4.z, acc[2][2]); acc[2][3] = fmaf(a4.z, b4.w, acc[2][3]);
            acc[3][0] = fmaf(a4.w, b4.x, acc[3][0]); acc[3][1] = fmaf(a4.w, b4.y, acc[3][1]);
            acc[3][2] = fmaf(a4.w, b4.z, acc[3][2]); acc[3][3] = fmaf(a4.w, b4.w, acc[3][3]);
        }
    }

    int sec = o0 >> 8;                 // 0=q, 1=k, 2=v (tile never crosses)
    int ocb = (o0 & 255) + tx * 4;     // channel within section
    int head = ocb >> 5, d = ocb & 31;
    float* dst = (sec == 0) ? g_q : ((sec == 1) ? g_k : g_v);
    float scale = (sec == 0) ? 0.17677669529663687f : 1.0f;
    float4 bv4 = *(const float4*)(bias + o0 + tx * 4);
    int w = m0 >> 9;
#pragma unroll
    for (int q = 0; q < 4; q++) {
        int t = m0 + ty * 4 + q;
        int n = t & 511;
        float4 r;
        r.x = (acc[q][0] + bv4.x) * scale;
        r.y = (acc[q][1] + bv4.y) * scale;
        r.z = (acc[q][2] + bv4.z) * scale;
        r.w = (acc[q][3] + bv4.w) * scale;
        *(float4*)&dst[(((size_t)w * 8 + head) * 512 + n) * 32 + d] = r;
    }
}

// ---------------------------------------------------------------------------
// Attention: one block per (window, head). 256 threads, 2 q-rows/thread.
// Pass 1: scores = qK^T + bias + mask -> track row max, spill scores.
// Pass 2: p = exp(s - m), l += p, acc += p*V; out = acc / l.
// K then V staged in the same 64KB dynamic smem buffer (broadcast LDS.128).
// ---------------------------------------------------------------------------
__global__ void attn_kernel() {
    extern __shared__ float kvs[];     // 512*32 floats = 64 KB
    __shared__ int rid_s[512];
    int bx = blockIdx.x;               // w*8 + h
    int w = bx >> 3, h = bx & 7;
    int tid = threadIdx.x;             // 256

    // region ids for shift mask
    int wh = w >> 4, ww = (w >> 2) & 3, wd = w & 3;
    for (int n = tid; n < 512; n += 256) {
        int ih = n >> 6, iw = (n >> 3) & 7, id = n & 7;
        int rh = (wh < 3) ? 0 : (ih < 4 ? 1 : 2);
        int rw = (ww < 3) ? 0 : (iw < 4 ? 1 : 2);
        int rd = (wd < 3) ? 0 : (id < 4 ? 1 : 2);
        rid_s[n] = rh * 9 + rw * 3 + rd;
    }
    // stage K
    const float4* Kg = (const float4*)(g_k + (size_t)bx * 512 * 32);
    float4* kv4 = (float4*)kvs;
    for (int i = tid; i < 4096; i += 256) kv4[i] = Kg[i];

    // load my 2 q rows
    int r0 = tid, r1 = tid + 256;
    float q0[32], q1[32];
    const float* Qg = g_q + (size_t)bx * 512 * 32;
#pragma unroll
    for (int i = 0; i < 8; i++) {
        float4 a = *(const float4*)(Qg + (size_t)r0 * 32 + i * 4);
        q0[i * 4 + 0] = a.x; q0[i * 4 + 1] = a.y; q0[i * 4 + 2] = a.z; q0[i * 4 + 3] = a.w;
        float4 b = *(const float4*)(Qg + (size_t)r1 * 32 + i * 4);
        q1[i * 4 + 0] = b.x; q1[i * 4 + 1] = b.y; q1[i * 4 + 2] = b.z; q1[i * 4 + 3] = b.w;
    }
    __syncthreads();
    int rid0 = rid_s[r0], rid1 = rid_s[r1];
    float m0 = -1e30f, m1 = -1e30f;
    float* sc = g_sc + (size_t)bx * 512 * 512;
    const float* bTb = g_biasT + (size_t)h * 512 * 512;

    for (int j = 0; j < 512; j++) {
        float s0 = 0.f, s1 = 0.f;
        const float* kr = &kvs[j * 32];
#pragma unroll
        for (int d = 0; d < 32; d += 4) {
            float4 kk = *(const float4*)(kr + d);
            s0 = fmaf(q0[d + 0], kk.x, s0); s0 = fmaf(q0[d + 1], kk.y, s0);
            s0 = fmaf(q0[d + 2], kk.z, s0); s0 = fmaf(q0[d + 3], kk.w, s0);
            s1 = fmaf(q1[d + 0], kk.x, s1); s1 = fmaf(q1[d + 1], kk.y, s1);
            s1 = fmaf(q1[d + 2], kk.z, s1); s1 = fmaf(q1[d + 3], kk.w, s1);
        }
        const float* bT = bTb + (size_t)j * 512;
        float b0 = bT[r0], b1 = bT[r1];
        int rj = rid_s[j];
        s0 += b0 + ((rid0 == rj) ? 0.f : -100.f);
        s1 += b1 + ((rid1 == rj) ? 0.f : -100.f);
        m0 = fmaxf(m0, s0); m1 = fmaxf(m1, s1);
        sc[(size_t)j * 512 + r0] = s0;
        sc[(size_t)j * 512 + r1] = s1;
    }
    __syncthreads();
    // stage V into same buffer
    const float4* Vg = (const float4*)(g_v + (size_t)bx * 512 * 32);
    for (int i = tid; i < 4096; i += 256) kv4[i] = Vg[i];
    __syncthreads();

    float acc0[32], acc1[32];
#pragma unroll
    for (int d = 0; d < 32; d++) { acc0[d] = 0.f; acc1[d] = 0.f; }
    float l0 = 0.f, l1 = 0.f;
    const float LOG2E = 1.4426950408889634f;
    for (int j = 0; j < 512; j++) {
        float p0 = exp2f((sc[(size_t)j * 512 + r0] - m0) * LOG2E);
        float p1 = exp2f((sc[(size_t)j * 512 + r1] - m1) * LOG2E);
        l0 += p0; l1 += p1;
        const float* vr = &kvs[j * 32];
#pragma unroll
        for (int d = 0; d < 32; d += 4) {
            float4 vv = *(const float4*)(vr + d);
            acc0[d + 0] = fmaf(p0, vv.x, acc0[d + 0]); acc0[d + 1] = fmaf(p0, vv.y, acc0[d + 1]);
            acc0[d + 2] = fmaf(p0, vv.z, acc0[d + 2]); acc0[d + 3] = fmaf(p0, vv.w, acc0[d + 3]);
            acc1[d + 0] = fmaf(p1, vv.x, acc1[d + 0]); acc1[d + 1] = fmaf(p1, vv.y, acc1[d + 1]);
            acc1[d + 2] = fmaf(p1, vv.z, acc1[d + 2]); acc1[d + 3] = fmaf(p1, vv.w, acc1[d + 3]);
        }
    }
    float inv0 = 1.0f / l0, inv1 = 1.0f / l1;
    float* og = g_att + (size_t)w * 512 * 256 + h * 32;
#pragma unroll
    for (int d = 0; d < 32; d += 4) {
        float4 o0v, o1v;
        o0v.x = acc0[d] * inv0; o0v.y = acc0[d + 1] * inv0;
        o0v.z = acc0[d + 2] * inv0; o0v.w = acc0[d + 3] * inv0;
        *(float4*)(og + (size_t)r0 * 256 + d) = o0v;
        o1v.x = acc1[d] * inv1; o1v.y = acc1[d + 1] * inv1;
        o1v.z = acc1[d + 2] * inv1; o1v.w = acc1[d + 3] * inv1;
        *(float4*)(og + (size_t)r1 * 256 + d) = o1v;
    }
}

// ---------------------------------------------------------------------------
// Proj GEMM: out[tokoff[t] + o] = sum_c g_att[t][c] * Wp[o][c] + bp[o]
// M=32768, N=256, K=256. Scatter via tokoff = reverse shift + un-window.
// ---------------------------------------------------------------------------
__global__ void proj_gemm_kernel(const float* __restrict__ W,
                                 const float* __restrict__ bias,
                                 float* __restrict__ out) {
    __shared__ float As[16 * 68];
    __shared__ float Bs[16 * 68];
    int tid = threadIdx.x;
    int m0 = blockIdx.x * 64, o0 = blockIdx.y * 64;
    int lr = tid >> 2, lc = (tid & 3) * 4;
    const float* aptr = g_att + (size_t)(m0 + lr) * 256 + lc;
    const float* bptr = W + (size_t)(o0 + lr) * 256 + lc;
    int tx = tid & 15, ty = tid >> 4;
    float acc[4][4];
#pragma unroll
    for (int a = 0; a < 4; a++)
#pragma unroll
        for (int b = 0; b < 4; b++) acc[a][b] = 0.f;

    for (int k0 = 0; k0 < 256; k0 += 16) {
        float4 av = *(const float4*)(aptr + k0);
        float4 bv = *(const float4*)(bptr + k0);
        __syncthreads();
        As[(lc + 0) * 68 + lr] = av.x; As[(lc + 1) * 68 + lr] = av.y;
        As[(lc + 2) * 68 + lr] = av.z; As[(lc + 3) * 68 + lr] = av.w;
        Bs[(lc + 0) * 68 + lr] = bv.x; Bs[(lc + 1) * 68 + lr] = bv.y;
        Bs[(lc + 2) * 68 + lr] = bv.z; Bs[(lc + 3) * 68 + lr] = bv.w;
        __syncthreads();
#pragma unroll
        for (int kk = 0; kk < 16; kk++) {
            float4 a4 = *(const float4*)&As[kk * 68 + ty * 4];
            float4 b4 = *(const float4*)&Bs[kk * 68 + tx * 4];
            acc[0][0] = fmaf(a4.x, b4.x, acc[0][0]); acc[0][1] = fmaf(a4.x, b4.y, acc[0][1]);
            acc[0][2] = fmaf(a4.x, b4.z, acc[0][2]); acc[0][3] = fmaf(a4.x, b4.w, acc[0][3]);
            acc[1][0] = fmaf(a4.y, b4.x, acc[1][0]); acc[1][1] = fmaf(a4.y, b4.y, acc[1][1]);
            acc[1][2] = fmaf(a4.y, b4.z, acc[1][2]); acc[1][3] = fmaf(a4.y, b4.w, acc[1][3]);
            acc[2][0] = fmaf(a4.z, b4.x, acc[2][0]); acc[2][1] = fmaf(a4.z, b4.y, acc[2][1]);
            acc[2][2] = fmaf(a4.z, b4.z, acc[2][2]); acc[2][3] = fmaf(a4.z, b4.w, acc[2][3]);
            acc[3][0] = fmaf(a4.w, b4.x, acc[3][0]); acc[3][1] = fmaf(a4.w, b4.y, acc[3][1]);
            acc[3][2] = fmaf(a4.w, b4.z, acc[3][2]); acc[3][3] = fmaf(a4.w, b4.w, acc[3][3]);
        }
    }

    int oc = o0 + tx * 4;
    float4 bv4 = *(const float4*)(bias + oc);
#pragma unroll
    for (int q = 0; q < 4; q++) {
        int t = m0 + ty * 4 + q;
        int off = g_tokoff[t] + oc;
        float4 r;
        r.x = acc[q][0] + bv4.x;
        r.y = acc[q][1] + bv4.y;
        r.z = acc[q][2] + bv4.z;
        r.w = acc[q][3] + bv4.w;
        *(float4*)&out[off] = r;
    }
}

extern "C" void kernel_launch(void* const* d_in, const int* in_sizes, int n_in,
                              void* d_out, int out_size) {
    const float* x      = (const float*)d_in[0];
    const float* qkv_w  = (const float*)d_in[1];
    const float* qkv_b  = (const float*)d_in[2];
    const float* proj_w = (const float*)d_in[3];
    const float* proj_b = (const float*)d_in[4];
    const float* rpb    = (const float*)d_in[5];
    float* out = (float*)d_out;

    cudaFuncSetAttribute(attn_kernel, cudaFuncAttributeMaxDynamicSharedMemorySize, 65536);

    prep_kernel<<<512, 256>>>(rpb);
    qkv_gemm_kernel<<<dim3(512, 12), 256>>>(x, qkv_w, qkv_b);
    attn_kernel<<<512, 256, 65536>>>();
    proj_gemm_kernel<<<dim3(512, 4), 256>>>(proj_w, proj_b, out);
}

// round 2
// speedup vs baseline: 1.3416x; 1.3416x over previous
#include <cuda_runtime.h>
#include <math.h>

// Problem constants
#define NWIN 64
#define NTOK 512
#define NHEAD 8
#define HDIM 32
#define CDIM 256

// Scratch (device globals -- no allocation allowed)
__device__ float g_q[NWIN * NHEAD * NTOK * HDIM];     // 33.5 MB
__device__ float g_k[NWIN * NHEAD * NTOK * HDIM];     // 33.5 MB
__device__ float g_v[NWIN * NHEAD * NTOK * HDIM];     // 33.5 MB
__device__ float g_biasT[NHEAD * NTOK * NTOK];        // 8.4 MB, biasT[h][j][i]
__device__ float g_att[NWIN * NTOK * CDIM];           // 33.5 MB, token-major
__device__ int   g_tokoff[NWIN * NTOK];               // token -> x/out element offset

// ---------------------------------------------------------------------------
// Prep: relative-position bias table (transposed) + token offset table.
// ---------------------------------------------------------------------------
__global__ void prep_kernel(const float* __restrict__ rpb) {
    int j = blockIdx.x;          // 0..511
    int tid = threadIdx.x;       // 0..255
    int j0 = j >> 6, j1 = (j >> 3) & 7, j2 = j & 7;
#pragma unroll
    for (int t = 0; t < 2; t++) {
        int i = tid + t * 256;
        int i0 = i >> 6, i1 = (i >> 3) & 7, i2 = i & 7;
        int idx = (i0 - j0 + 7) * 225 + (i1 - j1 + 7) * 15 + (i2 - j2 + 7);
        const float4* r = (const float4*)(rpb + idx * 8);
        float4 ra = r[0], rb = r[1];
        float vals[8] = {ra.x, ra.y, ra.z, ra.w, rb.x, rb.y, rb.z, rb.w};
#pragma unroll
        for (int hh = 0; hh < 8; hh++)
            g_biasT[((size_t)hh * 512 + j) * 512 + i] = vals[hh];
    }
    int gid = j * 256 + tid;
    if (gid < NWIN * NTOK) {
        int w = gid >> 9, n = gid & 511;
        int wh = w >> 4, ww = (w >> 2) & 3, wd = w & 3;
        int ih = n >> 6, iw = (n >> 3) & 7, id = n & 7;
        int gh = (wh * 8 + ih + 4) & 31;
        int gw = (ww * 8 + iw + 4) & 31;
        int gd = (wd * 8 + id + 4) & 31;
        g_tokoff[gid] = ((gh * 32 + gw) * 32 + gd) * 256;
    }
}

// ---------------------------------------------------------------------------
// QKV GEMM (unchanged from R1 -- ~92% of fp32 FMA roofline already)
// ---------------------------------------------------------------------------
__global__ void qkv_gemm_kernel(const float* __restrict__ x,
                                const float* __restrict__ W,
                                const float* __restrict__ bias) {
    __shared__ float As[16 * 68];
    __shared__ float Bs[16 * 68];
    int tid = threadIdx.x;
    int m0 = blockIdx.x * 64, o0 = blockIdx.y * 64;
    int lr = tid >> 2, lc = (tid & 3) * 4;
    const float* aptr = x + g_tokoff[m0 + lr] + lc;
    const float* bptr = W + (size_t)(o0 + lr) * 256 + lc;
    int tx = tid & 15, ty = tid >> 4;
    float acc[4][4];
#pragma unroll
    for (int a = 0; a < 4; a++)
#pragma unroll
        for (int b = 0; b < 4; b++) acc[a][b] = 0.f;

    for (int k0 = 0; k0 < 256; k0 += 16) {
        float4 av = *(const float4*)(aptr + k0);
        float4 bv = *(const float4*)(bptr + k0);
        __syncthreads();
        As[(lc + 0) * 68 + lr] = av.x; As[(lc + 1) * 68 + lr] = av.y;
        As[(lc + 2) * 68 + lr] = av.z; As[(lc + 3) * 68 + lr] = av.w;
        Bs[(lc + 0) * 68 + lr] = bv.x; Bs[(lc + 1) * 68 + lr] = bv.y;
        Bs[(lc + 2) * 68 + lr] = bv.z; Bs[(lc + 3) * 68 + lr] = bv.w;
        __syncthreads();
#pragma unroll
        for (int kk = 0; kk < 16; kk++) {
            float4 a4 = *(const float4*)&As[kk * 68 + ty * 4];
            float4 b4 = *(const float4*)&Bs[kk * 68 + tx * 4];
            acc[0][0] = fmaf(a4.x, b4.x, acc[0][0]); acc[0][1] = fmaf(a4.x, b4.y, acc[0][1]);
            acc[0][2] = fmaf(a4.x, b4.z, acc[0][2]); acc[0][3] = fmaf(a4.x, b4.w, acc[0][3]);
            acc[1][0] = fmaf(a4.y, b4.x, acc[1][0]); acc[1][1] = fmaf(a4.y, b4.y, acc[1][1]);
            acc[1][2] = fmaf(a4.y, b4.z, acc[1][2]); acc[1][3] = fmaf(a4.y, b4.w, acc[1][3]);
            acc[2][0] = fmaf(a4.z, b4.x, acc[2][0]); acc[2][1] = fmaf(a4.z, b4.y, acc[2][1]);
            acc[2][2] = fmaf(a4.z, b4.z, acc[2][2]); acc[2][3] = fmaf(a4.z, b4.w, acc[2][3]);
            acc[3][0] = fmaf(a4.w, b4.x, acc[3][0]); acc[3][1] = fmaf(a4.w, b4.y, acc[3][1]);
            acc[3][2] = fmaf(a4.w, b4.z, acc[3][2]); acc[3][3] = fmaf(a4.w, b4.w, acc[3][3]);
        }
    }

    int sec = o0 >> 8;                 // 0=q, 1=k, 2=v
    int ocb = (o0 & 255) + tx * 4;
    int head = ocb >> 5, d = ocb & 31;
    float* dst = (sec == 0) ? g_q : ((sec == 1) ? g_k : g_v);
    float scale = (sec == 0) ? 0.17677669529663687f : 1.0f;
    float4 bv4 = *(const float4*)(bias + o0 + tx * 4);
    int w = m0 >> 9;
#pragma unroll
    for (int q = 0; q < 4; q++) {
        int t = m0 + ty * 4 + q;
        int n = t & 511;
        float4 r;
        r.x = (acc[q][0] + bv4.x) * scale;
        r.y = (acc[q][1] + bv4.y) * scale;
        r.z = (acc[q][2] + bv4.z) * scale;
        r.w = (acc[q][3] + bv4.w) * scale;
        *(float4*)&dst[(((size_t)w * 8 + head) * 512 + n) * 32 + d] = r;
    }
}

// ---------------------------------------------------------------------------
// Attention: SINGLE PASS, no max subtraction (scores provably small; mask
// term -100 underflows exp harmlessly). One block per (window, head),
// 256 threads, 2 q-rows/thread. K (64KB) + V (64KB) both resident in smem.
//   l += exp(s);  acc += exp(s) * v;  out = acc / l.
// 4 partial score accumulators per row break the FMA RAW chain (lat4/rt2).
// Per-j bias load (L2-resident) prefetched one iteration ahead.
// ---------------------------------------------------------------------------
__global__ void __launch_bounds__(256, 1) attn_kernel() {
    extern __shared__ float smemf[];   // [0,16384) = K, [16384,32768) = V
    __shared__ int rid_s[512];
    float* Ks = smemf;
    float* Vs = smemf + 16384;
    int bx = blockIdx.x;               // w*8 + h
    int w = bx >> 3, h = bx & 7;
    int tid = threadIdx.x;             // 256

    // region ids for the cyclic-shift mask
    int wh = w >> 4, ww = (w >> 2) & 3, wd = w & 3;
    for (int n = tid; n < 512; n += 256) {
        int ih = n >> 6, iw = (n >> 3) & 7, id = n & 7;
        int rh = (wh < 3) ? 0 : (ih < 4 ? 1 : 2);
        int rw = (ww < 3) ? 0 : (iw < 4 ? 1 : 2);
        int rd = (wd < 3) ? 0 : (id < 4 ? 1 : 2);
        rid_s[n] = rh * 9 + rw * 3 + rd;
    }

    // stage K and V
    const float4* Kg = (const float4*)(g_k + (size_t)bx * 512 * 32);
    const float4* Vg = (const float4*)(g_v + (size_t)bx * 512 * 32);
    float4* K4 = (float4*)Ks;
    float4* V4 = (float4*)Vs;
    for (int i = tid; i < 4096; i += 256) {
        K4[i] = Kg[i];
        V4[i] = Vg[i];
    }

    // my 2 q rows
    int r0 = tid, r1 = tid + 256;
    float q0[32], q1[32];
    const float* Qg = g_q + (size_t)bx * 512 * 32;
#pragma unroll
    for (int i = 0; i < 8; i++) {
        float4 a = *(const float4*)(Qg + (size_t)r0 * 32 + i * 4);
        q0[i * 4 + 0] = a.x; q0[i * 4 + 1] = a.y; q0[i * 4 + 2] = a.z; q0[i * 4 + 3] = a.w;
        float4 b = *(const float4*)(Qg + (size_t)r1 * 32 + i * 4);
        q1[i * 4 + 0] = b.x; q1[i * 4 + 1] = b.y; q1[i * 4 + 2] = b.z; q1[i * 4 + 3] = b.w;
    }
    __syncthreads();

    int rid0 = rid_s[r0], rid1 = rid_s[r1];
    const float* bTb = g_biasT + (size_t)h * 512 * 512;

    float acc0[32], acc1[32];
#pragma unroll
    for (int d = 0; d < 32; d++) { acc0[d] = 0.f; acc1[d] = 0.f; }
    float l0 = 0.f, l1 = 0.f;
    const float LOG2E = 1.4426950408889634f;

    // prefetch bias for j=0
    float b0 = bTb[r0];
    float b1 = bTb[r1];

    for (int j = 0; j < 512; j++) {
        // prefetch next-iteration bias (L2 latency ~234cyc hidden by body)
        float bn0 = 0.f, bn1 = 0.f;
        if (j < 511) {
            const float* bT = bTb + (size_t)(j + 1) * 512;
            bn0 = bT[r0];
            bn1 = bT[r1];
        }

        // scores with 4-way partial accumulation per row
        const float* kr = &Ks[j * 32];
        float s0a = 0.f, s0b = 0.f, s0c = 0.f, s0d = 0.f;
        float s1a = 0.f, s1b = 0.f, s1c = 0.f, s1d = 0.f;
#pragma unroll
        for (int d = 0; d < 32; d += 16) {
            float4 k0v = *(const float4*)(kr + d + 0);
            float4 k1v = *(const float4*)(kr + d + 4);
            float4 k2v = *(const float4*)(kr + d + 8);
            float4 k3v = *(const float4*)(kr + d + 12);
            s0a = fmaf(q0[d + 0], k0v.x, s0a); s0a = fmaf(q0[d + 1], k0v.y, s0a);
            s0a = fmaf(q0[d + 2], k0v.z, s0a); s0a = fmaf(q0[d + 3], k0v.w, s0a);
            s0b = fmaf(q0[d + 4], k1v.x, s0b); s0b = fmaf(q0[d + 5], k1v.y, s0b);
            s0b = fmaf(q0[d + 6], k1v.z, s0b); s0b = fmaf(q0[d + 7], k1v.w, s0b);
            s0c = fmaf(q0[d + 8], k2v.x, s0c); s0c = fmaf(q0[d + 9], k2v.y, s0c);
            s0c = fmaf(q0[d + 10], k2v.z, s0c); s0c = fmaf(q0[d + 11], k2v.w, s0c);
            s0d = fmaf(q0[d + 12], k3v.x, s0d); s0d = fmaf(q0[d + 13], k3v.y, s0d);
            s0d = fmaf(q0[d + 14], k3v.z, s0d); s0d = fmaf(q0[d + 15], k3v.w, s0d);
            s1a = fmaf(q1[d + 0], k0v.x, s1a); s1a = fmaf(q1[d + 1], k0v.y, s1a);
            s1a = fmaf(q1[d + 2], k0v.z, s1a); s1a = fmaf(q1[d + 3], k0v.w, s1a);
            s1b = fmaf(q1[d + 4], k1v.x, s1b); s1b = fmaf(q1[d + 5], k1v.y, s1b);
            s1b = fmaf(q1[d + 6], k1v.z, s1b); s1b = fmaf(q1[d + 7], k1v.w, s1b);
            s1c = fmaf(q1[d + 8], k2v.x, s1c); s1c = fmaf(q1[d + 9], k2v.y, s1c);
            s1c = fmaf(q1[d + 10], k2v.z, s1c); s1c = fmaf(q1[d + 11], k2v.w, s1c);
            s1d = fmaf(q1[d + 12], k3v.x, s1d); s1d = fmaf(q1[d + 13], k3v.y, s1d);
            s1d = fmaf(q1[d + 14], k3v.z, s1d); s1d = fmaf(q1[d + 15], k3v.w, s1d);
        }
        int rj = rid_s[j];
        float s0 = (s0a + s0b) + (s0c + s0d) + b0 + ((rid0 == rj) ? 0.f : -100.f);
        float s1 = (s1a + s1b) + (s1c + s1d) + b1 + ((rid1 == rj) ? 0.f : -100.f);

        float p0 = exp2f(s0 * LOG2E);
        float p1 = exp2f(s1 * LOG2E);
        l0 += p0; l1 += p1;

        const float* vr = &Vs[j * 32];
#pragma unroll
        for (int d = 0; d < 32; d += 4) {
            float4 vv = *(const float4*)(vr + d);
            acc0[d + 0] = fmaf(p0, vv.x, acc0[d + 0]); acc0[d + 1] = fmaf(p0, vv.y, acc0[d + 1]);
            acc0[d + 2] = fmaf(p0, vv.z, acc0[d + 2]); acc0[d + 3] = fmaf(p0, vv.w, acc0[d + 3]);
            acc1[d + 0] = fmaf(p1, vv.x, acc1[d + 0]); acc1[d + 1] = fmaf(p1, vv.y, acc1[d + 1]);
            acc1[d + 2] = fmaf(p1, vv.z, acc1[d + 2]); acc1[d + 3] = fmaf(p1, vv.w, acc1[d + 3]);
        }
        b0 = bn0; b1 = bn1;
    }

    float inv0 = 1.0f / l0, inv1 = 1.0f / l1;
    float* og = g_att + (size_t)w * 512 * 256 + h * 32;
#pragma unroll
    for (int d = 0; d < 32; d += 4) {
        float4 o0v, o1v;
        o0v.x = acc0[d] * inv0; o0v.y = acc0[d + 1] * inv0;
        o0v.z = acc0[d + 2] * inv0; o0v.w = acc0[d + 3] * inv0;
        *(float4*)(og + (size_t)r0 * 256 + d) = o0v;
        o1v.x = acc1[d] * inv1; o1v.y = acc1[d + 1] * inv1;
        o1v.z = acc1[d + 2] * inv1; o1v.w = acc1[d + 3] * inv1;
        *(float4*)(og + (size_t)r1 * 256 + d) = o1v;
    }
}

// ---------------------------------------------------------------------------
// Proj GEMM (unchanged from R1)
// ---------------------------------------------------------------------------
__global__ void proj_gemm_kernel(const float* __restrict__ W,
                                 const float* __restrict__ bias,
                                 float* __restrict__ out) {
    __shared__ float As[16 * 68];
    __shared__ float Bs[16 * 68];
    int tid = threadIdx.x;
    int m0 = blockIdx.x * 64, o0 = blockIdx.y * 64;
    int lr = tid >> 2, lc = (tid & 3) * 4;
    const float* aptr = g_att + (size_t)(m0 + lr) * 256 + lc;
    const float* bptr = W + (size_t)(o0 + lr) * 256 + lc;
    int tx = tid & 15, ty = tid >> 4;
    float acc[4][4];
#pragma unroll
    for (int a = 0; a < 4; a++)
#pragma unroll
        for (int b = 0; b < 4; b++) acc[a][b] = 0.f;

    for (int k0 = 0; k0 < 256; k0 += 16) {
        float4 av = *(const float4*)(aptr + k0);
        float4 bv = *(const float4*)(bptr + k0);
        __syncthreads();
        As[(lc + 0) * 68 + lr] = av.x; As[(lc + 1) * 68 + lr] = av.y;
        As[(lc + 2) * 68 + lr] = av.z; As[(lc + 3) * 68 + lr] = av.w;
        Bs[(lc + 0) * 68 + lr] = bv.x; Bs[(lc + 1) * 68 + lr] = bv.y;
        Bs[(lc + 2) * 68 + lr] = bv.z; Bs[(lc + 3) * 68 + lr] = bv.w;
        __syncthreads();
#pragma unroll
        for (int kk = 0; kk < 16; kk++) {
            float4 a4 = *(const float4*)&As[kk * 68 + ty * 4];
            float4 b4 = *(const float4*)&Bs[kk * 68 + tx * 4];
            acc[0][0] = fmaf(a4.x, b4.x, acc[0][0]); acc[0][1] = fmaf(a4.x, b4.y, acc[0][1]);
            acc[0][2] = fmaf(a4.x, b4.z, acc[0][2]); acc[0][3] = fmaf(a4.x, b4.w, acc[0][3]);
            acc[1][0] = fmaf(a4.y, b4.x, acc[1][0]); acc[1][1] = fmaf(a4.y, b4.y, acc[1][1]);
            acc[1][2] = fmaf(a4.y, b4.z, acc[1][2]); acc[1][3] = fmaf(a4.y, b4.w, acc[1][3]);
            acc[2][0] = fmaf(a4.z, b4.x, acc[2][0]); acc[2][1] = fmaf(a4.z, b4.y, acc[2][1]);
            acc[2][2] = fmaf(a4.z, b4.z, acc[2][2]); acc[2][3] = fmaf(a4.z, b4.w, acc[2][3]);
            acc[3][0] = fmaf(a4.w, b4.x, acc[3][0]); acc[3][1] = fmaf(a4.w, b4.y, acc[3][1]);
            acc[3][2] = fmaf(a4.w, b4.z, acc[3][2]); acc[3][3] = fmaf(a4.w, b4.w, acc[3][3]);
        }
    }

    int oc = o0 + tx * 4;
    float4 bv4 = *(const float4*)(bias + oc);
#pragma unroll
    for (int q = 0; q < 4; q++) {
        int t = m0 + ty * 4 + q;
        int off = g_tokoff[t] + oc;
        float4 r;
        r.x = acc[q][0] + bv4.x;
        r.y = acc[q][1] + bv4.y;
        r.z = acc[q][2] + bv4.z;
        r.w = acc[q][3] + bv4.w;
        *(float4*)&out[off] = r;
    }
}

extern "C" void kernel_launch(void* const* d_in, const int* in_sizes, int n_in,
                              void* d_out, int out_size) {
    const float* x      = (const float*)d_in[0];
    const float* qkv_w  = (const float*)d_in[1];
    const float* qkv_b  = (const float*)d_in[2];
    const float* proj_w = (const float*)d_in[3];
    const float* proj_b = (const float*)d_in[4];
    const float* rpb    = (const float*)d_in[5];
    float* out = (float*)d_out;

    cudaFuncSetAttribute(attn_kernel, cudaFuncAttributeMaxDynamicSharedMemorySize, 131072);

    prep_kernel<<<512, 256>>>(rpb);
    qkv_gemm_kernel<<<dim3(512, 12), 256>>>(x, qkv_w, qkv_b);
    attn_kernel<<<512, 256, 131072>>>();
    proj_gemm_kernel<<<dim3(512, 4), 256>>>(proj_w, proj_b, out);
}

// round 5
// speedup vs baseline: 1.6015x; 1.1937x over previous
#include <cuda_runtime.h>
#include <cuda_bf16.h>
#include <math.h>
#include <stdint.h>

// Problem constants
#define NWIN 64
#define NTOK 512
#define NHEAD 8
#define HDIM 32
#define CDIM 256
#define KCAT 768            // 3 * 256 (bf16-split K concatenation)
#define MTOT 32768          // NWIN*NTOK

// Scratch (device globals -- no allocation allowed)
__device__ float g_q[NWIN * NHEAD * NTOK * HDIM];
__device__ float g_k[NWIN * NHEAD * NTOK * HDIM];
__device__ float g_v[NWIN * NHEAD * NTOK * HDIM];
__device__ float g_biasT[NHEAD * NTOK * NTOK];
__device__ float g_att[NWIN * NTOK * CDIM];
__device__ int   g_tokoff[NWIN * NTOK];
__device__ __nv_bfloat16 g_acat[(size_t)MTOT * KCAT];   // activations (hi|hi|lo)
__device__ __nv_bfloat16 g_bcat[(size_t)768 * KCAT];    // weights (hi|lo|hi)

__device__ __forceinline__ uint32_t smem_u32(const void* p) {
    uint32_t a;
    asm("{ .reg .u64 t; cvta.to.shared.u64 t, %1; cvt.u32.u64 %0, t; }" : "=r"(a) : "l"(p));
    return a;
}

// ---------------------------------------------------------------------------
// Prep: biasT + tokoff
// ---------------------------------------------------------------------------
__global__ void prep_kernel(const float* __restrict__ rpb) {
    int j = blockIdx.x;
    int tid = threadIdx.x;
    int j0 = j >> 6, j1 = (j >> 3) & 7, j2 = j & 7;
#pragma unroll
    for (int t = 0; t < 2; t++) {
        int i = tid + t * 256;
        int i0 = i >> 6, i1 = (i >> 3) & 7, i2 = i & 7;
        int idx = (i0 - j0 + 7) * 225 + (i1 - j1 + 7) * 15 + (i2 - j2 + 7);
        const float4* r = (const float4*)(rpb + idx * 8);
        float4 ra = r[0], rb = r[1];
        float vals[8] = {ra.x, ra.y, ra.z, ra.w, rb.x, rb.y, rb.z, rb.w};
#pragma unroll
        for (int hh = 0; hh < 8; hh++)
            g_biasT[((size_t)hh * 512 + j) * 512 + i] = vals[hh];
    }
    int gid = j * 256 + tid;
    if (gid < NWIN * NTOK) {
        int w = gid >> 9, n = gid & 511;
        int wh = w >> 4, ww = (w >> 2) & 3, wd = w & 3;
        int ih = n >> 6, iw = (n >> 3) & 7, id = n & 7;
        int gh = (wh * 8 + ih + 4) & 31;
        int gw = (ww * 8 + iw + 4) & 31;
        int gd = (wd * 8 + id + 4) & 31;
        g_tokoff[gid] = ((gh * 32 + gw) * 32 + gd) * 256;
    }
}

// ---------------------------------------------------------------------------
// Conversions: fp32 -> bf16 3-term split, K-concatenated.
// gather=1: read src (x) gathered via tokoff. gather=0: read g_att directly
// (device-side symbol -- passing g_att from host passes the host shadow!).
// ---------------------------------------------------------------------------
__global__ void conv_a_kernel(const float* __restrict__ src, int gather) {
    int row = blockIdx.x * 4 + (threadIdx.x >> 6);
    int c4 = (threadIdx.x & 63) * 4;
    const float* sp = gather ? (src + g_tokoff[row]) : (g_att + (size_t)row * 256);
    float4 v = *(const float4*)(sp + c4);
    union { __nv_bfloat16 h[4]; uint2 u; } H, L;
    H.h[0] = __float2bfloat16(v.x); L.h[0] = __float2bfloat16(v.x - __bfloat162float(H.h[0]));
    H.h[1] = __float2bfloat16(v.y); L.h[1] = __float2bfloat16(v.y - __bfloat162float(H.h[1]));
    H.h[2] = __float2bfloat16(v.z); L.h[2] = __float2bfloat16(v.z - __bfloat162float(H.h[2]));
    H.h[3] = __float2bfloat16(v.w); L.h[3] = __float2bfloat16(v.w - __bfloat162float(H.h[3]));
    __nv_bfloat16* dst = g_acat + (size_t)row * KCAT;
    *(uint2*)(dst + c4)       = H.u;
    *(uint2*)(dst + 256 + c4) = H.u;
    *(uint2*)(dst + 512 + c4) = L.u;
}

__global__ void conv_w_kernel(const float* __restrict__ W) {
    int row = blockIdx.x;
    int c4 = threadIdx.x * 4;   // block 64
    float4 v = *(const float4*)(W + (size_t)row * 256 + c4);
    union { __nv_bfloat16 h[4]; uint2 u; } H, L;
    H.h[0] = __float2bfloat16(v.x); L.h[0] = __float2bfloat16(v.x - __bfloat162float(H.h[0]));
    H.h[1] = __float2bfloat16(v.y); L.h[1] = __float2bfloat16(v.y - __bfloat162float(H.h[1]));
    H.h[2] = __float2bfloat16(v.z); L.h[2] = __float2bfloat16(v.z - __bfloat162float(H.h[2]));
    H.h[3] = __float2bfloat16(v.w); L.h[3] = __float2bfloat16(v.w - __bfloat162float(H.h[3]));
    __nv_bfloat16* dst = g_bcat + (size_t)row * KCAT;
    *(uint2*)(dst + c4)       = H.u;
    *(uint2*)(dst + 256 + c4) = L.u;
    *(uint2*)(dst + 512 + c4) = H.u;
}

// ---------------------------------------------------------------------------
// HMMA GEMM: D[128x128 fp32] = A_cat[m0:,768] x B_cat[n0:,768]^T
// mma.sync.m16n8k16 bf16, 8 warps (4x2), warp tile 32x64.
// smem: padded rows (72 bf16 = 144B) -> conflict-free ldmatrix; K-chunk 64,
// double buffered: A0@0 A1@18432 B0@36864 B1@55296 (73728 B total).
// mode 0: -> g_q/g_k/g_v (+bias, q-scale). mode 1: -> out via tokoff (+bias).
// ---------------------------------------------------------------------------
__global__ void __launch_bounds__(256) hmma_gemm_kernel(const float* __restrict__ bias,
                                                        float* __restrict__ out, int mode) {
    extern __shared__ __align__(16) char smem[];
    uint32_t sbase = smem_u32(smem);
    int tid = threadIdx.x;
    int lane = tid & 31, wid = tid >> 5;
    int wm = wid & 3, wn = wid >> 2;
    int m0 = blockIdx.x * 128, n0 = blockIdx.y * 128;

    // global load assignment: 2 threads per row, 4 uint4 (64B) each
    int lr = tid >> 1, lh = tid & 1;
    const uint4* Ag = (const uint4*)(g_acat + (size_t)(m0 + lr) * KCAT) + lh * 4;
    const uint4* Bg = (const uint4*)(g_bcat + (size_t)(n0 + lr) * KCAT) + lh * 4;
    uint32_t stoff = (uint32_t)(lr * 144 + lh * 64);

    // ldmatrix lane offsets
    uint32_t aoff = (uint32_t)((((lane & 7) + ((lane >> 3) & 1) * 8) * 144) + (lane >> 4) * 16);
    uint32_t boff = (uint32_t)((((lane & 7) + (lane >> 4) * 8) * 144) + ((lane >> 3) & 1) * 16);

    float acc[2][8][4];
#pragma unroll
    for (int a = 0; a < 2; a++)
#pragma unroll
        for (int b = 0; b < 8; b++)
#pragma unroll
            for (int c = 0; c < 4; c++) acc[a][b][c] = 0.f;

    uint4 ra[4], rb[4];
    // prologue: chunk 0 -> buffer 0
#pragma unroll
    for (int i = 0; i < 4; i++) { ra[i] = Ag[i]; rb[i] = Bg[i]; }
#pragma unroll
    for (int i = 0; i < 4; i++) {
        asm volatile("st.shared.v4.b32 [%0], {%1,%2,%3,%4};"
                     :: "r"(sbase + stoff + i * 16),
                        "r"(ra[i].x), "r"(ra[i].y), "r"(ra[i].z), "r"(ra[i].w) : "memory");
        asm volatile("st.shared.v4.b32 [%0], {%1,%2,%3,%4};"
                     :: "r"(sbase + 36864u + stoff + i * 16),
                        "r"(rb[i].x), "r"(rb[i].y), "r"(rb[i].z), "r"(rb[i].w) : "memory");
    }
    __syncthreads();

#pragma unroll 1
    for (int c = 0; c < 12; c++) {
        if (c < 11) {
#pragma unroll
            for (int i = 0; i < 4; i++) {
                ra[i] = Ag[(c + 1) * 8 + i];
                rb[i] = Bg[(c + 1) * 8 + i];
            }
        }
        uint32_t Ab = sbase + (uint32_t)(c & 1) * 18432u;
        uint32_t Bb = sbase + 36864u + (uint32_t)(c & 1) * 18432u;
        uint32_t Abw = Ab + (uint32_t)(wm * 32) * 144u + aoff;
        uint32_t Bbw = Bb + (uint32_t)(wn * 64) * 144u + boff;
#pragma unroll
        for (int ks = 0; ks < 4; ks++) {
            uint32_t afr[2][4];
#pragma unroll
            for (int mt = 0; mt < 2; mt++) {
                uint32_t addr = Abw + (uint32_t)(mt * 16) * 144u + ks * 32u;
                asm volatile("ldmatrix.sync.aligned.m8n8.x4.shared.b16 {%0,%1,%2,%3}, [%4];"
                             : "=r"(afr[mt][0]), "=r"(afr[mt][1]), "=r"(afr[mt][2]), "=r"(afr[mt][3])
                             : "r"(addr));
            }
            uint32_t bfr[8][2];
#pragma unroll
            for (int p = 0; p < 4; p++) {
                uint32_t addr = Bbw + (uint32_t)(p * 16) * 144u + ks * 32u;
                asm volatile("ldmatrix.sync.aligned.m8n8.x4.shared.b16 {%0,%1,%2,%3}, [%4];"
                             : "=r"(bfr[2 * p][0]), "=r"(bfr[2 * p][1]),
                               "=r"(bfr[2 * p + 1][0]), "=r"(bfr[2 * p + 1][1])
                             : "r"(addr));
            }
#pragma unroll
            for (int mt = 0; mt < 2; mt++)
#pragma unroll
                for (int nt = 0; nt < 8; nt++) {
                    asm volatile(
                        "mma.sync.aligned.m16n8k16.row.col.f32.bf16.bf16.f32 "
                        "{%0,%1,%2,%3}, {%4,%5,%6,%7}, {%8,%9}, {%0,%1,%2,%3};"
                        : "+f"(acc[mt][nt][0]), "+f"(acc[mt][nt][1]),
                          "+f"(acc[mt][nt][2]), "+f"(acc[mt][nt][3])
                        : "r"(afr[mt][0]), "r"(afr[mt][1]), "r"(afr[mt][2]), "r"(afr[mt][3]),
                          "r"(bfr[nt][0]), "r"(bfr[nt][1]));
                }
        }
        if (c < 11) {
            uint32_t nb = (uint32_t)((c + 1) & 1);
#pragma unroll
            for (int i = 0; i < 4; i++) {
                asm volatile("st.shared.v4.b32 [%0], {%1,%2,%3,%4};"
                             :: "r"(sbase + nb * 18432u + stoff + i * 16),
                                "r"(ra[i].x), "r"(ra[i].y), "r"(ra[i].z), "r"(ra[i].w) : "memory");
                asm volatile("st.shared.v4.b32 [%0], {%1,%2,%3,%4};"
                             :: "r"(sbase + 36864u + nb * 18432u + stoff + i * 16),
                                "r"(rb[i].x), "r"(rb[i].y), "r"(rb[i].z), "r"(rb[i].w) : "memory");
            }
            __syncthreads();
        }
    }

    // Epilogue. D frag: c0,c1 -> (quad, tg*2/+1); c2,c3 -> (quad+8, ...)
    int quad = lane >> 2, tg = lane & 3;
#pragma unroll
    for (int mt = 0; mt < 2; mt++) {
        int rbase = m0 + wm * 32 + mt * 16 + quad;
#pragma unroll
        for (int nt = 0; nt < 8; nt++) {
            int col = n0 + wn * 64 + nt * 8 + tg * 2;
            float2 bb = *(const float2*)(bias + col);
            if (mode == 0) {
                int sec = n0 >> 8;
                float scale = (sec == 0) ? 0.17677669529663687f : 1.0f;
                float* dst = (sec == 0) ? g_q : ((sec == 1) ? g_k : g_v);
                int head = (col & 255) >> 5, dd = col & 31;
#pragma unroll
                for (int hf = 0; hf < 2; hf++) {
                    int rr = rbase + hf * 8;
                    int w = rr >> 9, nn = rr & 511;
                    float2 o;
                    o.x = (acc[mt][nt][hf * 2 + 0] + bb.x) * scale;
                    o.y = (acc[mt][nt][hf * 2 + 1] + bb.y) * scale;
                    *(float2*)(dst + (((size_t)w * 8 + head) * 512 + nn) * 32 + dd) = o;
                }
            } else {
#pragma unroll
                for (int hf = 0; hf < 2; hf++) {
                    int rr = rbase + hf * 8;
                    int off = g_tokoff[rr] + col;
                    float2 o;
                    o.x = acc[mt][nt][hf * 2 + 0] + bb.x;
                    o.y = acc[mt][nt][hf * 2 + 1] + bb.y;
                    *(float2*)(out + off) = o;
                }
            }
        }
    }
}

// ---------------------------------------------------------------------------
// Attention (unchanged from R2): single pass, no max subtraction.
// ---------------------------------------------------------------------------
__global__ void __launch_bounds__(256, 1) attn_kernel() {
    extern __shared__ float smemf[];
    __shared__ int rid_s[512];
    float* Ks = smemf;
    float* Vs = smemf + 16384;
    int bx = blockIdx.x;
    int w = bx >> 3, h = bx & 7;
    int tid = threadIdx.x;

    int wh = w >> 4, ww = (w >> 2) & 3, wd = w & 3;
    for (int n = tid; n < 512; n += 256) {
        int ih = n >> 6, iw = (n >> 3) & 7, id = n & 7;
        int rh = (wh < 3) ? 0 : (ih < 4 ? 1 : 2);
        int rw = (ww < 3) ? 0 : (iw < 4 ? 1 : 2);
        int rd = (wd < 3) ? 0 : (id < 4 ? 1 : 2);
        rid_s[n] = rh * 9 + rw * 3 + rd;
    }

    const float4* Kg = (const float4*)(g_k + (size_t)bx * 512 * 32);
    const float4* Vg = (const float4*)(g_v + (size_t)bx * 512 * 32);
    float4* K4 = (float4*)Ks;
    float4* V4 = (float4*)Vs;
    for (int i = tid; i < 4096; i += 256) {
        K4[i] = Kg[i];
        V4[i] = Vg[i];
    }

    int r0 = tid, r1 = tid + 256;
    float q0[32], q1[32];
    const float* Qg = g_q + (size_t)bx * 512 * 32;
#pragma unroll
    for (int i = 0; i < 8; i++) {
        float4 a = *(const float4*)(Qg + (size_t)r0 * 32 + i * 4);
        q0[i * 4 + 0] = a.x; q0[i * 4 + 1] = a.y; q0[i * 4 + 2] = a.z; q0[i * 4 + 3] = a.w;
        float4 b = *(const float4*)(Qg + (size_t)r1 * 32 + i * 4);
        q1[i * 4 + 0] = b.x; q1[i * 4 + 1] = b.y; q1[i * 4 + 2] = b.z; q1[i * 4 + 3] = b.w;
    }
    __syncthreads();

    int rid0 = rid_s[r0], rid1 = rid_s[r1];
    const float* bTb = g_biasT + (size_t)h * 512 * 512;

    float acc0[32], acc1[32];
#pragma unroll
    for (int d = 0; d < 32; d++) { acc0[d] = 0.f; acc1[d] = 0.f; }
    float l0 = 0.f, l1 = 0.f;
    const float LOG2E = 1.4426950408889634f;

    float b0 = bTb[r0];
    float b1 = bTb[r1];

    for (int j = 0; j < 512; j++) {
        float bn0 = 0.f, bn1 = 0.f;
        if (j < 511) {
            const float* bT = bTb + (size_t)(j + 1) * 512;
            bn0 = bT[r0];
            bn1 = bT[r1];
        }

        const float* kr = &Ks[j * 32];
        float s0a = 0.f, s0b = 0.f, s0c = 0.f, s0d = 0.f;
        float s1a = 0.f, s1b = 0.f, s1c = 0.f, s1d = 0.f;
#pragma unroll
        for (int d = 0; d < 32; d += 16) {
            float4 k0v = *(const float4*)(kr + d + 0);
            float4 k1v = *(const float4*)(kr + d + 4);
            float4 k2v = *(const float4*)(kr + d + 8);
            float4 k3v = *(const float4*)(kr + d + 12);
            s0a = fmaf(q0[d + 0], k0v.x, s0a); s0a = fmaf(q0[d + 1], k0v.y, s0a);
            s0a = fmaf(q0[d + 2], k0v.z, s0a); s0a = fmaf(q0[d + 3], k0v.w, s0a);
            s0b = fmaf(q0[d + 4], k1v.x, s0b); s0b = fmaf(q0[d + 5], k1v.y, s0b);
            s0b = fmaf(q0[d + 6], k1v.z, s0b); s0b = fmaf(q0[d + 7], k1v.w, s0b);
            s0c = fmaf(q0[d + 8], k2v.x, s0c); s0c = fmaf(q0[d + 9], k2v.y, s0c);
            s0c = fmaf(q0[d + 10], k2v.z, s0c); s0c = fmaf(q0[d + 11], k2v.w, s0c);
            s0d = fmaf(q0[d + 12], k3v.x, s0d); s0d = fmaf(q0[d + 13], k3v.y, s0d);
            s0d = fmaf(q0[d + 14], k3v.z, s0d); s0d = fmaf(q0[d + 15], k3v.w, s0d);
            s1a = fmaf(q1[d + 0], k0v.x, s1a); s1a = fmaf(q1[d + 1], k0v.y, s1a);
            s1a = fmaf(q1[d + 2], k0v.z, s1a); s1a = fmaf(q1[d + 3], k0v.w, s1a);
            s1b = fmaf(q1[d + 4], k1v.x, s1b); s1b = fmaf(q1[d + 5], k1v.y, s1b);
            s1b = fmaf(q1[d + 6], k1v.z, s1b); s1b = fmaf(q1[d + 7], k1v.w, s1b);
            s1c = fmaf(q1[d + 8], k2v.x, s1c); s1c = fmaf(q1[d + 9], k2v.y, s1c);
            s1c = fmaf(q1[d + 10], k2v.z, s1c); s1c = fmaf(q1[d + 11], k2v.w, s1c);
            s1d = fmaf(q1[d + 12], k3v.x, s1d); s1d = fmaf(q1[d + 13], k3v.y, s1d);
            s1d = fmaf(q1[d + 14], k3v.z, s1d); s1d = fmaf(q1[d + 15], k3v.w, s1d);
        }
        int rj = rid_s[j];
        float s0 = (s0a + s0b) + (s0c + s0d) + b0 + ((rid0 == rj) ? 0.f : -100.f);
        float s1 = (s1a + s1b) + (s1c + s1d) + b1 + ((rid1 == rj) ? 0.f : -100.f);

        float p0 = exp2f(s0 * LOG2E);
        float p1 = exp2f(s1 * LOG2E);
        l0 += p0; l1 += p1;

        const float* vr = &Vs[j * 32];
#pragma unroll
        for (int d = 0; d < 32; d += 4) {
            float4 vv = *(const float4*)(vr + d);
            acc0[d + 0] = fmaf(p0, vv.x, acc0[d + 0]); acc0[d + 1] = fmaf(p0, vv.y, acc0[d + 1]);
            acc0[d + 2] = fmaf(p0, vv.z, acc0[d + 2]); acc0[d + 3] = fmaf(p0, vv.w, acc0[d + 3]);
            acc1[d + 0] = fmaf(p1, vv.x, acc1[d + 0]); acc1[d + 1] = fmaf(p1, vv.y, acc1[d + 1]);
            acc1[d + 2] = fmaf(p1, vv.z, acc1[d + 2]); acc1[d + 3] = fmaf(p1, vv.w, acc1[d + 3]);
        }
        b0 = bn0; b1 = bn1;
    }

    float inv0 = 1.0f / l0, inv1 = 1.0f / l1;
    float* og = g_att + (size_t)w * 512 * 256 + h * 32;
#pragma unroll
    for (int d = 0; d < 32; d += 4) {
        float4 o0v, o1v;
        o0v.x = acc0[d] * inv0; o0v.y = acc0[d + 1] * inv0;
        o0v.z = acc0[d + 2] * inv0; o0v.w = acc0[d + 3] * inv0;
        *(float4*)(og + (size_t)r0 * 256 + d) = o0v;
        o1v.x = acc1[d] * inv1; o1v.y = acc1[d + 1] * inv1;
        o1v.z = acc1[d + 2] * inv1; o1v.w = acc1[d + 3] * inv1;
        *(float4*)(og + (size_t)r1 * 256 + d) = o1v;
    }
}

extern "C" void kernel_launch(void* const* d_in, const int* in_sizes, int n_in,
                              void* d_out, int out_size) {
    const float* x      = (const float*)d_in[0];
    const float* qkv_w  = (const float*)d_in[1];
    const float* qkv_b  = (const float*)d_in[2];
    const float* proj_w = (const float*)d_in[3];
    const float* proj_b = (const float*)d_in[4];
    const float* rpb    = (const float*)d_in[5];
    float* out = (float*)d_out;

    cudaFuncSetAttribute(attn_kernel, cudaFuncAttributeMaxDynamicSharedMemorySize, 131072);
    cudaFuncSetAttribute(hmma_gemm_kernel, cudaFuncAttributeMaxDynamicSharedMemorySize, 73728);

    prep_kernel<<<512, 256>>>(rpb);
    conv_w_kernel<<<768, 64>>>(qkv_w);
    conv_a_kernel<<<8192, 256>>>(x, 1);
    hmma_gemm_kernel<<<dim3(256, 6), 256, 73728>>>(qkv_b, nullptr, 0);
    attn_kernel<<<512, 256, 131072>>>();
    conv_w_kernel<<<256, 64>>>(proj_w);
    conv_a_kernel<<<8192, 256>>>(x, 0);   // reads g_att internally (device symbol)
    hmma_gemm_kernel<<<dim3(256, 2), 256, 73728>>>(proj_b, out, 1);
}

// round 7
// speedup vs baseline: 2.6889x; 1.6789x over previous
#include <cuda_runtime.h>
#include <cuda_bf16.h>
#include <math.h>
#include <stdint.h>

// Problem constants
#define NWIN 64
#define NTOK 512
#define NHEAD 8
#define HDIM 32
#define CDIM 256
#define KCAT 768
#define MTOT 32768

#define LOG2E 1.4426950408889634f
#define QSCALE (0.17677669529663687f * 1.4426950408889634f)

// Scratch (device globals)
__device__ __nv_bfloat16 g_qh[(size_t)512 * 512 * 32];   // [bx][tok][32]
__device__ __nv_bfloat16 g_ql[(size_t)512 * 512 * 32];
__device__ __nv_bfloat16 g_kh[(size_t)512 * 512 * 32];
__device__ __nv_bfloat16 g_kl[(size_t)512 * 512 * 32];
__device__ __nv_bfloat16 g_vth[(size_t)512 * 32 * 512];  // [bx][d][tok] (transposed)
__device__ __nv_bfloat16 g_vtl[(size_t)512 * 32 * 512];
__device__ float g_bfrag[(size_t)8 * 8 * 32 * 64 * 128]; // [cfg][h][ib][jb][half][row][jp][comp]
__device__ float g_att[NWIN * NTOK * CDIM];
__device__ int   g_tokoff[NWIN * NTOK];
__device__ __nv_bfloat16 g_acat[(size_t)MTOT * KCAT];
__device__ __nv_bfloat16 g_bcat[(size_t)768 * KCAT];

__device__ __forceinline__ uint32_t smem_u32(const void* p) {
    uint32_t a;
    asm("{ .reg .u64 t; cvta.to.shared.u64 t, %1; cvt.u32.u64 %0, t; }" : "=r"(a) : "l"(p));
    return a;
}
__device__ __forceinline__ void ldmx4(uint32_t* r, uint32_t addr) {
    asm volatile("ldmatrix.sync.aligned.m8n8.x4.shared.b16 {%0,%1,%2,%3}, [%4];"
                 : "=r"(r[0]), "=r"(r[1]), "=r"(r[2]), "=r"(r[3]) : "r"(addr));
}
__device__ __forceinline__ void st128(uint32_t addr, uint4 v) {
    asm volatile("st.shared.v4.b32 [%0], {%1,%2,%3,%4};"
                 :: "r"(addr), "r"(v.x), "r"(v.y), "r"(v.z), "r"(v.w) : "memory");
}
__device__ __forceinline__ void mma16816(float* c, const uint32_t* a, const uint32_t* b) {
    asm volatile("mma.sync.aligned.m16n8k16.row.col.f32.bf16.bf16.f32 "
                 "{%0,%1,%2,%3}, {%4,%5,%6,%7}, {%8,%9}, {%0,%1,%2,%3};"
                 : "+f"(c[0]), "+f"(c[1]), "+f"(c[2]), "+f"(c[3])
                 : "r"(a[0]), "r"(a[1]), "r"(a[2]), "r"(a[3]), "r"(b[0]), "r"(b[1]));
}
__device__ __forceinline__ void split2(float f0, float f1, uint32_t& hi, uint32_t& lo) {
    __nv_bfloat16 h0 = __float2bfloat16(f0), h1 = __float2bfloat16(f1);
    __nv_bfloat16 l0 = __float2bfloat16(f0 - __bfloat162float(h0));
    __nv_bfloat16 l1 = __float2bfloat16(f1 - __bfloat162float(h1));
    uint16_t uh0 = *(uint16_t*)&h0, uh1 = *(uint16_t*)&h1;
    uint16_t ul0 = *(uint16_t*)&l0, ul1 = *(uint16_t*)&l1;
    hi = (uint32_t)uh0 | ((uint32_t)uh1 << 16);
    lo = (uint32_t)ul0 | ((uint32_t)ul1 << 16);
}

// ---------------------------------------------------------------------------
// Prep: token offset table (cyclic shift fold)
// ---------------------------------------------------------------------------
__global__ void prep_tok_kernel() {
    int gid = blockIdx.x * 256 + threadIdx.x;
    int w = gid >> 9, n = gid & 511;
    int wh = w >> 4, ww = (w >> 2) & 3, wd = w & 3;
    int ih = n >> 6, iw = (n >> 3) & 7, id = n & 7;
    int gh = (wh * 8 + ih + 4) & 31;
    int gw = (ww * 8 + iw + 4) & 31;
    int gd = (wd * 8 + id + 4) & 31;
    g_tokoff[gid] = ((gh * 32 + gw) * 32 + gd) * 256;
}

// ---------------------------------------------------------------------------
// Prep: (bias + mask)*LOG2E baked into mma D-fragment layout, per window cfg.
// ---------------------------------------------------------------------------
__global__ void prep_bias_kernel(const float* __restrict__ rpb) {
    int cfg = blockIdx.x >> 9;
    int j = blockIdx.x & 511;
    int tid = threadIdx.x;
    int ch = (cfg >> 2) & 1, cw = (cfg >> 1) & 1, cd = cfg & 1;
    int j0 = j >> 6, j1 = (j >> 3) & 7, j2 = j & 7;
    int rj = (ch ? (j0 < 4 ? 1 : 2) : 0) * 9 + (cw ? (j1 < 4 ? 1 : 2) : 0) * 3
           + (cd ? (j2 < 4 ? 1 : 2) : 0);
    int jb = j >> 3, jp = (j & 7) >> 1, comp = j & 1;
#pragma unroll
    for (int t = 0; t < 2; t++) {
        int i = tid + t * 256;
        int i0 = i >> 6, i1 = (i >> 3) & 7, i2 = i & 7;
        int ri = (ch ? (i0 < 4 ? 1 : 2) : 0) * 9 + (cw ? (i1 < 4 ? 1 : 2) : 0) * 3
               + (cd ? (i2 < 4 ? 1 : 2) : 0);
        float m = (ri == rj) ? 0.f : -100.f;
        int idx = (i0 - j0 + 7) * 225 + (i1 - j1 + 7) * 15 + (i2 - j2 + 7);
        const float4* r = (const float4*)(rpb + idx * 8);
        float4 ra = r[0], rb = r[1];
        float vals[8] = {ra.x, ra.y, ra.z, ra.w, rb.x, rb.y, rb.z, rb.w};
        int ib = i >> 4, half = (i & 15) >> 3, row = i & 7;
#pragma unroll
        for (int h = 0; h < 8; h++) {
            size_t fidx = (((((size_t)cfg * 8 + h) * 32 + ib) * 64 + jb) * 128)
                        + half * 64 + row * 8 + jp * 2 + comp;
            g_bfrag[fidx] = (vals[h] + m) * LOG2E;
        }
    }
}

// ---------------------------------------------------------------------------
// Conversions: fp32 -> bf16 3-term split, K-concatenated (for the GEMMs).
// ---------------------------------------------------------------------------
__global__ void conv_a_kernel(const float* __restrict__ src, int gather) {
    int row = blockIdx.x * 4 + (threadIdx.x >> 6);
    int c4 = (threadIdx.x & 63) * 4;
    const float* sp = gather ? (src + g_tokoff[row]) : (g_att + (size_t)row * 256);
    float4 v = *(const float4*)(sp + c4);
    union { __nv_bfloat16 h[4]; uint2 u; } H, L;
    H.h[0] = __float2bfloat16(v.x); L.h[0] = __float2bfloat16(v.x - __bfloat162float(H.h[0]));
    H.h[1] = __float2bfloat16(v.y); L.h[1] = __float2bfloat16(v.y - __bfloat162float(H.h[1]));
    H.h[2] = __float2bfloat16(v.z); L.h[2] = __float2bfloat16(v.z - __bfloat162float(H.h[2]));
    H.h[3] = __float2bfloat16(v.w); L.h[3] = __float2bfloat16(v.w - __bfloat162float(H.h[3]));
    __nv_bfloat16* dst = g_acat + (size_t)row * KCAT;
    *(uint2*)(dst + c4)       = H.u;
    *(uint2*)(dst + 256 + c4) = H.u;
    *(uint2*)(dst + 512 + c4) = L.u;
}

__global__ void conv_w_kernel(const float* __restrict__ W) {
    int row = blockIdx.x;
    int c4 = threadIdx.x * 4;
    float4 v = *(const float4*)(W + (size_t)row * 256 + c4);
    union { __nv_bfloat16 h[4]; uint2 u; } H, L;
    H.h[0] = __float2bfloat16(v.x); L.h[0] = __float2bfloat16(v.x - __bfloat162float(H.h[0]));
    H.h[1] = __float2bfloat16(v.y); L.h[1] = __float2bfloat16(v.y - __bfloat162float(H.h[1]));
    H.h[2] = __float2bfloat16(v.z); L.h[2] = __float2bfloat16(v.z - __bfloat162float(H.h[2]));
    H.h[3] = __float2bfloat16(v.w); L.h[3] = __float2bfloat16(v.w - __bfloat162float(H.h[3]));
    __nv_bfloat16* dst = g_bcat + (size_t)row * KCAT;
    *(uint2*)(dst + c4)       = H.u;
    *(uint2*)(dst + 256 + c4) = L.u;
    *(uint2*)(dst + 512 + c4) = H.u;
}

// ---------------------------------------------------------------------------
// HMMA GEMM (body identical to R5; mode-0 epilogue emits split bf16 q/k
// (+LOG2E*scale on q) and transposed split bf16 v).
// ---------------------------------------------------------------------------
__global__ void __launch_bounds__(256) hmma_gemm_kernel(const float* __restrict__ bias,
                                                        float* __restrict__ out, int mode) {
    extern __shared__ __align__(16) char smem[];
    uint32_t sbase = smem_u32(smem);
    int tid = threadIdx.x;
    int lane = tid & 31, wid = tid >> 5;
    int wm = wid & 3, wn = wid >> 2;
    int m0 = blockIdx.x * 128, n0 = blockIdx.y * 128;

    int lr = tid >> 1, lh = tid & 1;
    const uint4* Ag = (const uint4*)(g_acat + (size_t)(m0 + lr) * KCAT) + lh * 4;
    const uint4* Bg = (const uint4*)(g_bcat + (size_t)(n0 + lr) * KCAT) + lh * 4;
    uint32_t stoff = (uint32_t)(lr * 144 + lh * 64);

    uint32_t aoff = (uint32_t)((((lane & 7) + ((lane >> 3) & 1) * 8) * 144) + (lane >> 4) * 16);
    uint32_t boff = (uint32_t)((((lane & 7) + (lane >> 4) * 8) * 144) + ((lane >> 3) & 1) * 16);

    float acc[2][8][4];
#pragma unroll
    for (int a = 0; a < 2; a++)
#pragma unroll
        for (int b = 0; b < 8; b++)
#pragma unroll
            for (int c = 0; c < 4; c++) acc[a][b][c] = 0.f;

    uint4 ra[4], rb[4];
#pragma unroll
    for (int i = 0; i < 4; i++) { ra[i] = Ag[i]; rb[i] = Bg[i]; }
#pragma unroll
    for (int i = 0; i < 4; i++) {
        st128(sbase + stoff + i * 16, ra[i]);
        st128(sbase + 36864u + stoff + i * 16, rb[i]);
    }
    __syncthreads();

#pragma unroll 1
    for (int c = 0; c < 12; c++) {
        if (c < 11) {
#pragma unroll
            for (int i = 0; i < 4; i++) {
                ra[i] = Ag[(c + 1) * 8 + i];
                rb[i] = Bg[(c + 1) * 8 + i];
            }
        }
        uint32_t Ab = sbase + (uint32_t)(c & 1) * 18432u;
        uint32_t Bb = sbase + 36864u + (uint32_t)(c & 1) * 18432u;
        uint32_t Abw = Ab + (uint32_t)(wm * 32) * 144u + aoff;
        uint32_t Bbw = Bb + (uint32_t)(wn * 64) * 144u + boff;
#pragma unroll
        for (int ks = 0; ks < 4; ks++) {
            uint32_t afr[2][4];
#pragma unroll
            for (int mt = 0; mt < 2; mt++)
                ldmx4(afr[mt], Abw + (uint32_t)(mt * 16) * 144u + ks * 32u);
            uint32_t bfr[8][2];
#pragma unroll
            for (int p = 0; p < 4; p++) {
                uint32_t t4[4];
                ldmx4(t4, Bbw + (uint32_t)(p * 16) * 144u + ks * 32u);
                bfr[2 * p][0] = t4[0]; bfr[2 * p][1] = t4[1];
                bfr[2 * p + 1][0] = t4[2]; bfr[2 * p + 1][1] = t4[3];
            }
#pragma unroll
            for (int mt = 0; mt < 2; mt++)
#pragma unroll
                for (int nt = 0; nt < 8; nt++)
                    mma16816(acc[mt][nt], afr[mt], bfr[nt]);
        }
        if (c < 11) {
            uint32_t nb = (uint32_t)((c + 1) & 1);
#pragma unroll
            for (int i = 0; i < 4; i++) {
                st128(sbase + nb * 18432u + stoff + i * 16, ra[i]);
                st128(sbase + 36864u + nb * 18432u + stoff + i * 16, rb[i]);
            }
            __syncthreads();
        }
    }

    int quad = lane >> 2, tg = lane & 3;
#pragma unroll
    for (int mt = 0; mt < 2; mt++) {
        int rbase = m0 + wm * 32 + mt * 16 + quad;
#pragma unroll
        for (int nt = 0; nt < 8; nt++) {
            int col = n0 + wn * 64 + nt * 8 + tg * 2;
            float2 bb = *(const float2*)(bias + col);
            if (mode == 0) {
                int sec = n0 >> 8;
                float sc = (sec == 0) ? QSCALE : 1.0f;
                int head = (col & 255) >> 5, dd = col & 31;
#pragma unroll
                for (int hf = 0; hf < 2; hf++) {
                    int rr = rbase + hf * 8;
                    int w = rr >> 9, nn = rr & 511;
                    size_t bxi = (size_t)(w * 8 + head);
                    float f0 = (acc[mt][nt][hf * 2 + 0] + bb.x) * sc;
                    float f1 = (acc[mt][nt][hf * 2 + 1] + bb.y) * sc;
                    uint32_t hi, lo;
                    split2(f0, f1, hi, lo);
                    if (sec <= 1) {
                        __nv_bfloat16* dh = (sec == 0 ? g_qh : g_kh) + (bxi * 512 + nn) * 32 + dd;
                        __nv_bfloat16* dl = (sec == 0 ? g_ql : g_kl) + (bxi * 512 + nn) * 32 + dd;
                        *(uint32_t*)dh = hi;
                        *(uint32_t*)dl = lo;
                    } else {
                        g_vth[(bxi * 32 + dd) * 512 + nn]     = *(__nv_bfloat16*)&hi;
                        g_vth[(bxi * 32 + dd + 1) * 512 + nn] = ((__nv_bfloat162*)&hi)->y;
                        g_vtl[(bxi * 32 + dd) * 512 + nn]     = *(__nv_bfloat16*)&lo;
                        g_vtl[(bxi * 32 + dd + 1) * 512 + nn] = ((__nv_bfloat162*)&lo)->y;
                    }
                }
            } else {
#pragma unroll
                for (int hf = 0; hf < 2; hf++) {
                    int rr = rbase + hf * 8;
                    int off = g_tokoff[rr] + col;
                    float2 o;
                    o.x = acc[mt][nt][hf * 2 + 0] + bb.x;
                    o.y = acc[mt][nt][hf * 2 + 1] + bb.y;
                    *(float2*)(out + off) = o;
                }
            }
        }
    }
}

// ---------------------------------------------------------------------------
// HMMA attention. Q/K smem rows padded to 80 B (16-aligned, conflict-free);
// V tiles 144 B stride. Layout: Qh 10240 | Ql 10240 | 2 x (Kh 5120 + Kl 5120
// + Vth 4608 + Vtl 4608 = 19456). Total 59392 B.
// ---------------------------------------------------------------------------
__global__ void __launch_bounds__(256) attn_mma_kernel() {
    extern __shared__ __align__(16) char sm[];
    uint32_t sb = smem_u32(sm);
    const int tid = threadIdx.x, lane = tid & 31, wid = tid >> 5;
    int bx = blockIdx.x >> 2, mt = blockIdx.x & 3;
    int w = bx >> 3, h = bx & 7;
    int cfg = (((w >> 4) == 3) ? 4 : 0) | ((((w >> 2) & 3) == 3) ? 2 : 0) | (((w & 3) == 3) ? 1 : 0);

    const uint32_t SQH = 0, SQL = 10240, SBUF = 20480, BSTR = 19456;
    const uint32_t KH = 0, KL = 5120, VTH = 10240, VTL = 14848;

    // load Q tiles (row stride 80 B)
#pragma unroll
    for (int u = 0; u < 2; u++) {
        int lin = tid + u * 256;
        int row = lin >> 2, seg = lin & 3;
        size_t src = ((size_t)bx * 512 + mt * 128 + row) * 32 + seg * 8;
        st128(sb + SQH + row * 80 + seg * 16, *(const uint4*)(g_qh + src));
        st128(sb + SQL + row * 80 + seg * 16, *(const uint4*)(g_ql + src));
    }

    int row_k = tid >> 2, seg_k = tid & 3;
    int row_v = tid >> 3, seg_v = tid & 7;
    size_t ksrc = (size_t)bx * 512 * 32 + (size_t)row_k * 32 + seg_k * 8;
    size_t vsrc = (size_t)bx * 32 * 512 + (size_t)row_v * 512 + seg_v * 8;
    uint32_t kdst = row_k * 80 + seg_k * 16;
    uint32_t vdst = row_v * 144 + seg_v * 16;

    uint4 ta, tb, tc, td;
    ta = *(const uint4*)(g_kh + ksrc);
    tb = *(const uint4*)(g_kl + ksrc);
    tc = *(const uint4*)(g_vth + vsrc);
    td = *(const uint4*)(g_vtl + vsrc);
    st128(sb + SBUF + KH + kdst, ta);
    st128(sb + SBUF + KL + kdst, tb);
    st128(sb + SBUF + VTH + vdst, tc);
    st128(sb + SBUF + VTL + vdst, td);
    __syncthreads();

    uint32_t aoff = (uint32_t)(((lane & 7) + ((lane >> 3) & 1) * 8) * 80 + (lane >> 4) * 16);
    uint32_t boff = (uint32_t)(((lane & 7) + (lane >> 4) * 8) * 80 + ((lane >> 3) & 1) * 16);
    uint32_t vboff = (uint32_t)(((lane & 7) + (lane >> 4) * 8) * 144 + ((lane >> 3) & 1) * 16);
    uint32_t qh[2][4], ql[2][4];
#pragma unroll
    for (int ks = 0; ks < 2; ks++) {
        ldmx4(qh[ks], sb + SQH + (uint32_t)(wid * 16) * 80 + aoff + ks * 32);
        ldmx4(ql[ks], sb + SQL + (uint32_t)(wid * 16) * 80 + aoff + ks * 32);
    }

    float oacc[4][4];
#pragma unroll
    for (int a = 0; a < 4; a++)
#pragma unroll
        for (int b = 0; b < 4; b++) oacc[a][b] = 0.f;
    float rs0 = 0.f, rs1 = 0.f;
    int quad = lane >> 2, tg = lane & 3;
    int ib = mt * 8 + wid;
    const float* bf = g_bfrag + ((((size_t)cfg * 8 + h) * 32 + ib) * 64) * 128;

#pragma unroll 1
    for (int jt = 0; jt < 8; jt++) {
        if (jt < 7) {
            size_t ks2 = ksrc + (size_t)(jt + 1) * 64 * 32;
            size_t vs2 = vsrc + (size_t)(jt + 1) * 64;
            ta = *(const uint4*)(g_kh + ks2);
            tb = *(const uint4*)(g_kl + ks2);
            tc = *(const uint4*)(g_vth + vs2);
            td = *(const uint4*)(g_vtl + vs2);
        }
        uint32_t B = sb + SBUF + (uint32_t)(jt & 1) * BSTR;

        // QK: S-frags
        float sacc[8][4];
#pragma unroll
        for (int a = 0; a < 8; a++)
#pragma unroll
            for (int b = 0; b < 4; b++) sacc[a][b] = 0.f;
#pragma unroll
        for (int ks = 0; ks < 2; ks++)
#pragma unroll
            for (int p = 0; p < 4; p++) {
                uint32_t bh[4], bl[4];
                ldmx4(bh, B + KH + (uint32_t)(p * 16) * 80 + boff + ks * 32);
                ldmx4(bl, B + KL + (uint32_t)(p * 16) * 80 + boff + ks * 32);
#pragma unroll
                for (int n2 = 0; n2 < 2; n2++) {
                    mma16816(sacc[2 * p + n2], qh[ks], &bh[n2 * 2]);
                    mma16816(sacc[2 * p + n2], qh[ks], &bl[n2 * 2]);
                    mma16816(sacc[2 * p + n2], ql[ks], &bh[n2 * 2]);
                }
            }

        // softmax + P split (D-frag -> A-frag identity)
        uint32_t aPhi[4][4], aPlo[4][4];
#pragma unroll
        for (int nt = 0; nt < 8; nt++) {
            const float2* bp = (const float2*)(bf + (size_t)(jt * 8 + nt) * 128);
            float2 b01 = bp[quad * 4 + tg];
            float2 b23 = bp[32 + quad * 4 + tg];
            float p0 = exp2f(sacc[nt][0] + b01.x);
            float p1 = exp2f(sacc[nt][1] + b01.y);
            float p2 = exp2f(sacc[nt][2] + b23.x);
            float p3 = exp2f(sacc[nt][3] + b23.y);
            rs0 += p0 + p1;
            rs1 += p2 + p3;
            int kt = nt >> 1, o = (nt & 1) * 2;
            split2(p0, p1, aPhi[kt][o], aPlo[kt][o]);
            split2(p2, p3, aPhi[kt][o + 1], aPlo[kt][o + 1]);
        }

        // PV
#pragma unroll
        for (int kt = 0; kt < 4; kt++)
#pragma unroll
            for (int np = 0; np < 2; np++) {
                uint32_t vh[4], vl[4];
                ldmx4(vh, B + VTH + (uint32_t)(np * 16) * 144 + vboff + kt * 32);
                ldmx4(vl, B + VTL + (uint32_t)(np * 16) * 144 + vboff + kt * 32);
#pragma unroll
                for (int n2 = 0; n2 < 2; n2++) {
                    mma16816(oacc[np * 2 + n2], aPhi[kt], &vh[n2 * 2]);
                    mma16816(oacc[np * 2 + n2], aPhi[kt], &vl[n2 * 2]);
                    mma16816(oacc[np * 2 + n2], aPlo[kt], &vh[n2 * 2]);
                }
            }

        if (jt < 7) {
            uint32_t B2 = sb + SBUF + (uint32_t)((jt + 1) & 1) * BSTR;
            st128(B2 + KH + kdst, ta);
            st128(B2 + KL + kdst, tb);
            st128(B2 + VTH + vdst, tc);
            st128(B2 + VTL + vdst, td);
            __syncthreads();
        }
    }

    rs0 += __shfl_xor_sync(0xFFFFFFFF, rs0, 1);
    rs0 += __shfl_xor_sync(0xFFFFFFFF, rs0, 2);
    rs1 += __shfl_xor_sync(0xFFFFFFFF, rs1, 1);
    rs1 += __shfl_xor_sync(0xFFFFFFFF, rs1, 2);
    float inv0 = 1.f / rs0, inv1 = 1.f / rs1;
    int qtok = mt * 128 + wid * 16 + quad;
    float* ob = g_att + (size_t)w * 512 * 256 + h * 32;
#pragma unroll
    for (int nt = 0; nt < 4; nt++) {
        float2 o0, o1;
        o0.x = oacc[nt][0] * inv0; o0.y = oacc[nt][1] * inv0;
        o1.x = oacc[nt][2] * inv1; o1.y = oacc[nt][3] * inv1;
        *(float2*)(ob + (size_t)qtok * 256 + nt * 8 + tg * 2) = o0;
        *(float2*)(ob + (size_t)(qtok + 8) * 256 + nt * 8 + tg * 2) = o1;
    }
}

extern "C" void kernel_launch(void* const* d_in, const int* in_sizes, int n_in,
                              void* d_out, int out_size) {
    const float* x      = (const float*)d_in[0];
    const float* qkv_w  = (const float*)d_in[1];
    const float* qkv_b  = (const float*)d_in[2];
    const float* proj_w = (const float*)d_in[3];
    const float* proj_b = (const float*)d_in[4];
    const float* rpb    = (const float*)d_in[5];
    float* out = (float*)d_out;

    cudaFuncSetAttribute(hmma_gemm_kernel, cudaFuncAttributeMaxDynamicSharedMemorySize, 73728);
    cudaFuncSetAttribute(attn_mma_kernel, cudaFuncAttributeMaxDynamicSharedMemorySize, 59392);

    prep_tok_kernel<<<128, 256>>>();
    prep_bias_kernel<<<4096, 256>>>(rpb);
    conv_w_kernel<<<768, 64>>>(qkv_w);
    conv_a_kernel<<<8192, 256>>>(x, 1);
    hmma_gemm_kernel<<<dim3(256, 6), 256, 73728>>>(qkv_b, nullptr, 0);
    attn_mma_kernel<<<2048, 256, 59392>>>();
    conv_w_kernel<<<256, 64>>>(proj_w);
    conv_a_kernel<<<8192, 256>>>(x, 0);   // reads g_att internally
    hmma_gemm_kernel<<<dim3(256, 2), 256, 73728>>>(proj_b, out, 1);
}

// round 8
// speedup vs baseline: 2.9636x; 1.1022x over previous
#include <cuda_runtime.h>
#include <cuda_bf16.h>
#include <math.h>
#include <stdint.h>

#define NWIN 64
#define NTOK 512
#define NHEAD 8
#define HDIM 32
#define CDIM 256
#define KCAT 768
#define MTOT 32768

#define LOG2E 1.4426950408889634f
#define QSCALE (0.17677669529663687f * 1.4426950408889634f)

__device__ __nv_bfloat16 g_qh[(size_t)512 * 512 * 32];
__device__ __nv_bfloat16 g_ql[(size_t)512 * 512 * 32];
__device__ __nv_bfloat16 g_kh[(size_t)512 * 512 * 32];
__device__ __nv_bfloat16 g_kl[(size_t)512 * 512 * 32];
__device__ __nv_bfloat16 g_vth[(size_t)512 * 32 * 512];
__device__ __nv_bfloat16 g_vtl[(size_t)512 * 32 * 512];
__device__ float g_bfrag[(size_t)8 * 8 * 32 * 64 * 128];
__device__ float g_att[NWIN * NTOK * CDIM];
__device__ int   g_tokoff[NWIN * NTOK];
__device__ __nv_bfloat16 g_acat[(size_t)MTOT * KCAT];
__device__ __nv_bfloat16 g_bcat[(size_t)768 * KCAT];

__device__ __forceinline__ uint32_t smem_u32(const void* p) {
    uint32_t a;
    asm("{ .reg .u64 t; cvta.to.shared.u64 t, %1; cvt.u32.u64 %0, t; }" : "=r"(a) : "l"(p));
    return a;
}
__device__ __forceinline__ void ldmx4(uint32_t* r, uint32_t addr) {
    asm volatile("ldmatrix.sync.aligned.m8n8.x4.shared.b16 {%0,%1,%2,%3}, [%4];"
                 : "=r"(r[0]), "=r"(r[1]), "=r"(r[2]), "=r"(r[3]) : "r"(addr));
}
__device__ __forceinline__ void st128(uint32_t addr, uint4 v) {
    asm volatile("st.shared.v4.b32 [%0], {%1,%2,%3,%4};"
                 :: "r"(addr), "r"(v.x), "r"(v.y), "r"(v.z), "r"(v.w) : "memory");
}
__device__ __forceinline__ void mma16816(float* c, const uint32_t* a, const uint32_t* b) {
    asm volatile("mma.sync.aligned.m16n8k16.row.col.f32.bf16.bf16.f32 "
                 "{%0,%1,%2,%3}, {%4,%5,%6,%7}, {%8,%9}, {%0,%1,%2,%3};"
                 : "+f"(c[0]), "+f"(c[1]), "+f"(c[2]), "+f"(c[3])
                 : "r"(a[0]), "r"(a[1]), "r"(a[2]), "r"(a[3]), "r"(b[0]), "r"(b[1]));
}
__device__ __forceinline__ void split2(float f0, float f1, uint32_t& hi, uint32_t& lo) {
    __nv_bfloat16 h0 = __float2bfloat16(f0), h1 = __float2bfloat16(f1);
    __nv_bfloat16 l0 = __float2bfloat16(f0 - __bfloat162float(h0));
    __nv_bfloat16 l1 = __float2bfloat16(f1 - __bfloat162float(h1));
    uint16_t uh0 = *(uint16_t*)&h0, uh1 = *(uint16_t*)&h1;
    uint16_t ul0 = *(uint16_t*)&l0, ul1 = *(uint16_t*)&l1;
    hi = (uint32_t)uh0 | ((uint32_t)uh1 << 16);
    lo = (uint32_t)ul0 | ((uint32_t)ul1 << 16);
}
#define CPA16(dst, src) \
    asm volatile("cp.async.cg.shared.global [%0], [%1], 16;" :: "r"(dst), "l"(src) : "memory")
#define CPC() asm volatile("cp.async.commit_group;" ::: "memory")
#define CPW0() asm volatile("cp.async.wait_group 0;" ::: "memory")

// ---------------------------------------------------------------------------
__global__ void prep_tok_kernel() {
    int gid = blockIdx.x * 256 + threadIdx.x;
    int w = gid >> 9, n = gid & 511;
    int wh = w >> 4, ww = (w >> 2) & 3, wd = w & 3;
    int ih = n >> 6, iw = (n >> 3) & 7, id = n & 7;
    int gh = (wh * 8 + ih + 4) & 31;
    int gw = (ww * 8 + iw + 4) & 31;
    int gd = (wd * 8 + id + 4) & 31;
    g_tokoff[gid] = ((gh * 32 + gw) * 32 + gd) * 256;
}

// ---------------------------------------------------------------------------
// prep_bias: coalesced rewrite. grid (cfg*512 + i), block 512 = (h, jb).
// Each thread emits 8 consecutive floats (j2 = 0..7) of one frag row.
// ---------------------------------------------------------------------------
__global__ void __launch_bounds__(512) prep_bias_kernel(const float* __restrict__ rpb) {
    int cfg = blockIdx.x >> 9, i = blockIdx.x & 511;
    int h = threadIdx.x >> 6, jb = threadIdx.x & 63;
    int ch = (cfg >> 2) & 1, cw = (cfg >> 1) & 1, cd = cfg & 1;
    int i0 = i >> 6, i1 = (i >> 3) & 7, i2 = i & 7;
    int ri = (ch ? (i0 < 4 ? 1 : 2) : 0) * 9 + (cw ? (i1 < 4 ? 1 : 2) : 0) * 3
           + (cd ? (i2 < 4 ? 1 : 2) : 0);
    int ib = i >> 4, half = (i & 15) >> 3, row = i & 7;
    int j0 = jb >> 3, j1 = jb & 7;
    int rjb = (ch ? (j0 < 4 ? 1 : 2) : 0) * 9 + (cw ? (j1 < 4 ? 1 : 2) : 0) * 3;
    int idxb = (i0 - j0 + 7) * 225 + (i1 - j1 + 7) * 15;
    float o[8];
#pragma unroll
    for (int j2 = 0; j2 < 8; j2++) {
        int rj = rjb + (cd ? (j2 < 4 ? 1 : 2) : 0);
        int idx = idxb + (i2 - j2 + 7);
        float m = (ri == rj) ? 0.f : -100.f;
        o[j2] = (rpb[idx * 8 + h] + m) * LOG2E;
    }
    size_t base = (((((size_t)cfg * 8 + h) * 32 + ib) * 64 + jb) * 128) + half * 64 + row * 8;
    *(float4*)(g_bfrag + base)     = make_float4(o[0], o[1], o[2], o[3]);
    *(float4*)(g_bfrag + base + 4) = make_float4(o[4], o[5], o[6], o[7]);
}

// ---------------------------------------------------------------------------
// Conversions (widened: 8 floats/thread, uint4 stores).
// conv_a: grid 4096, block 256 (8 rows x 32 thr). conv_w: grid N, block 32.
// ---------------------------------------------------------------------------
__global__ void conv_a_kernel(const float* __restrict__ src, int gather) {
    int row = blockIdx.x * 8 + (threadIdx.x >> 5);
    int c8 = (threadIdx.x & 31) * 8;
    const float* sp = gather ? (src + g_tokoff[row]) : (g_att + (size_t)row * 256);
    float4 v0 = *(const float4*)(sp + c8);
    float4 v1 = *(const float4*)(sp + c8 + 4);
    float f[8] = {v0.x, v0.y, v0.z, v0.w, v1.x, v1.y, v1.z, v1.w};
    union { __nv_bfloat16 h[8]; uint4 u; } H, L;
#pragma unroll
    for (int i = 0; i < 8; i++) {
        H.h[i] = __float2bfloat16(f[i]);
        L.h[i] = __float2bfloat16(f[i] - __bfloat162float(H.h[i]));
    }
    __nv_bfloat16* dst = g_acat + (size_t)row * KCAT;
    *(uint4*)(dst + c8)       = H.u;
    *(uint4*)(dst + 256 + c8) = H.u;
    *(uint4*)(dst + 512 + c8) = L.u;
}

__global__ void conv_w_kernel(const float* __restrict__ W) {
    int row = blockIdx.x;
    int c8 = threadIdx.x * 8;
    const float* sp = W + (size_t)row * 256 + c8;
    float4 v0 = *(const float4*)(sp);
    float4 v1 = *(const float4*)(sp + 4);
    float f[8] = {v0.x, v0.y, v0.z, v0.w, v1.x, v1.y, v1.z, v1.w};
    union { __nv_bfloat16 h[8]; uint4 u; } H, L;
#pragma unroll
    for (int i = 0; i < 8; i++) {
        H.h[i] = __float2bfloat16(f[i]);
        L.h[i] = __float2bfloat16(f[i] - __bfloat162float(H.h[i]));
    }
    __nv_bfloat16* dst = g_bcat + (size_t)row * KCAT;
    *(uint4*)(dst + c8)       = H.u;
    *(uint4*)(dst + 256 + c8) = L.u;
    *(uint4*)(dst + 512 + c8) = H.u;
}

// ---------------------------------------------------------------------------
// HMMA GEMM with cp.async staging, 2 CTAs/SM.
// ---------------------------------------------------------------------------
__global__ void __launch_bounds__(256, 2) hmma_gemm_kernel(const float* __restrict__ bias,
                                                           float* __restrict__ out, int mode) {
    extern __shared__ __align__(16) char smem[];
    uint32_t sbase = smem_u32(smem);
    int tid = threadIdx.x;
    int lane = tid & 31, wid = tid >> 5;
    int wm = wid & 3, wn = wid >> 2;
    int m0 = blockIdx.x * 128, n0 = blockIdx.y * 128;

    int lr = tid >> 1, lh = tid & 1;
    const char* Agb = (const char*)g_acat + (size_t)(m0 + lr) * 1536 + lh * 64;
    const char* Bgb = (const char*)g_bcat + (size_t)(n0 + lr) * 1536 + lh * 64;
    uint32_t stoff = (uint32_t)(lr * 144 + lh * 64);

    uint32_t aoff = (uint32_t)((((lane & 7) + ((lane >> 3) & 1) * 8) * 144) + (lane >> 4) * 16);
    uint32_t boff = (uint32_t)((((lane & 7) + (lane >> 4) * 8) * 144) + ((lane >> 3) & 1) * 16);

    float acc[2][8][4];
#pragma unroll
    for (int a = 0; a < 2; a++)
#pragma unroll
        for (int b = 0; b < 8; b++)
#pragma unroll
            for (int c = 0; c < 4; c++) acc[a][b][c] = 0.f;

    // prologue: chunk 0 -> buffer 0
#pragma unroll
    for (int i = 0; i < 4; i++) {
        CPA16(sbase + stoff + i * 16, Agb + i * 16);
        CPA16(sbase + 36864u + stoff + i * 16, Bgb + i * 16);
    }
    CPC();
    CPW0();
    __syncthreads();

#pragma unroll 1
    for (int c = 0; c < 12; c++) {
        if (c < 11) {
            uint32_t nb = (uint32_t)((c + 1) & 1);
            const char* As = Agb + (size_t)(c + 1) * 128;
            const char* Bs = Bgb + (size_t)(c + 1) * 128;
#pragma unroll
            for (int i = 0; i < 4; i++) {
                CPA16(sbase + nb * 18432u + stoff + i * 16, As + i * 16);
                CPA16(sbase + 36864u + nb * 18432u + stoff + i * 16, Bs + i * 16);
            }
            CPC();
        }
        uint32_t Ab = sbase + (uint32_t)(c & 1) * 18432u;
        uint32_t Bb = sbase + 36864u + (uint32_t)(c & 1) * 18432u;
        uint32_t Abw = Ab + (uint32_t)(wm * 32) * 144u + aoff;
        uint32_t Bbw = Bb + (uint32_t)(wn * 64) * 144u + boff;
#pragma unroll
        for (int ks = 0; ks < 4; ks++) {
            uint32_t afr[2][4];
#pragma unroll
            for (int mt = 0; mt < 2; mt++)
                ldmx4(afr[mt], Abw + (uint32_t)(mt * 16) * 144u + ks * 32u);
            uint32_t bfr[8][2];
#pragma unroll
            for (int p = 0; p < 4; p++) {
                uint32_t t4[4];
                ldmx4(t4, Bbw + (uint32_t)(p * 16) * 144u + ks * 32u);
                bfr[2 * p][0] = t4[0]; bfr[2 * p][1] = t4[1];
                bfr[2 * p + 1][0] = t4[2]; bfr[2 * p + 1][1] = t4[3];
            }
#pragma unroll
            for (int mt = 0; mt < 2; mt++)
#pragma unroll
                for (int nt = 0; nt < 8; nt++)
                    mma16816(acc[mt][nt], afr[mt], bfr[nt]);
        }
        if (c < 11) {
            CPW0();
            __syncthreads();
        }
    }

    int quad = lane >> 2, tg = lane & 3;
#pragma unroll
    for (int mt = 0; mt < 2; mt++) {
        int rbase = m0 + wm * 32 + mt * 16 + quad;
#pragma unroll
        for (int nt = 0; nt < 8; nt++) {
            int col = n0 + wn * 64 + nt * 8 + tg * 2;
            float2 bb = *(const float2*)(bias + col);
            if (mode == 0) {
                int sec = n0 >> 8;
                float sc = (sec == 0) ? QSCALE : 1.0f;
                int head = (col & 255) >> 5, dd = col & 31;
#pragma unroll
                for (int hf = 0; hf < 2; hf++) {
                    int rr = rbase + hf * 8;
                    int w = rr >> 9, nn = rr & 511;
                    size_t bxi = (size_t)(w * 8 + head);
                    float f0 = (acc[mt][nt][hf * 2 + 0] + bb.x) * sc;
                    float f1 = (acc[mt][nt][hf * 2 + 1] + bb.y) * sc;
                    uint32_t hi, lo;
                    split2(f0, f1, hi, lo);
                    if (sec <= 1) {
                        __nv_bfloat16* dh = (sec == 0 ? g_qh : g_kh) + (bxi * 512 + nn) * 32 + dd;
                        __nv_bfloat16* dl = (sec == 0 ? g_ql : g_kl) + (bxi * 512 + nn) * 32 + dd;
                        *(uint32_t*)dh = hi;
                        *(uint32_t*)dl = lo;
                    } else {
                        g_vth[(bxi * 32 + dd) * 512 + nn]     = *(__nv_bfloat16*)&hi;
                        g_vth[(bxi * 32 + dd + 1) * 512 + nn] = ((__nv_bfloat162*)&hi)->y;
                        g_vtl[(bxi * 32 + dd) * 512 + nn]     = *(__nv_bfloat16*)&lo;
                        g_vtl[(bxi * 32 + dd + 1) * 512 + nn] = ((__nv_bfloat162*)&lo)->y;
                    }
                }
            } else {
#pragma unroll
                for (int hf = 0; hf < 2; hf++) {
                    int rr = rbase + hf * 8;
                    int off = g_tokoff[rr] + col;
                    float2 o;
                    o.x = acc[mt][nt][hf * 2 + 0] + bb.x;
                    o.y = acc[mt][nt][hf * 2 + 1] + bb.y;
                    *(float2*)(out + off) = o;
                }
            }
        }
    }
}

// ---------------------------------------------------------------------------
// HMMA attention with cp.async staging, 2 CTAs/SM.
// ---------------------------------------------------------------------------
__global__ void __launch_bounds__(256, 2) attn_mma_kernel() {
    extern __shared__ __align__(16) char sm[];
    uint32_t sb = smem_u32(sm);
    const int tid = threadIdx.x, lane = tid & 31, wid = tid >> 5;
    int bx = blockIdx.x >> 2, mt = blockIdx.x & 3;
    int w = bx >> 3, h = bx & 7;
    int cfg = (((w >> 4) == 3) ? 4 : 0) | ((((w >> 2) & 3) == 3) ? 2 : 0) | (((w & 3) == 3) ? 1 : 0);

    const uint32_t SQH = 0, SQL = 10240, SBUF = 20480, BSTR = 19456;
    const uint32_t KH = 0, KL = 5120, VTH = 10240, VTL = 14848;

    int row_k = tid >> 2, seg_k = tid & 3;
    int row_v = tid >> 3, seg_v = tid & 7;
    const char* kga = (const char*)(g_kh + (size_t)bx * 512 * 32 + (size_t)row_k * 32 + seg_k * 8);
    const char* kgb = (const char*)(g_kl + (size_t)bx * 512 * 32 + (size_t)row_k * 32 + seg_k * 8);
    const char* vga = (const char*)(g_vth + (size_t)bx * 32 * 512 + (size_t)row_v * 512 + seg_v * 8);
    const char* vgb = (const char*)(g_vtl + (size_t)bx * 32 * 512 + (size_t)row_v * 512 + seg_v * 8);
    uint32_t kdst = row_k * 80 + seg_k * 16;
    uint32_t vdst = row_v * 144 + seg_v * 16;

    // prologue: jt=0 -> buffer 0
    CPA16(sb + SBUF + KH + kdst, kga);
    CPA16(sb + SBUF + KL + kdst, kgb);
    CPA16(sb + SBUF + VTH + vdst, vga);
    CPA16(sb + SBUF + VTL + vdst, vgb);
    CPC();

    // stage Q (row stride 80 B)
#pragma unroll
    for (int u = 0; u < 2; u++) {
        int lin = tid + u * 256;
        int row = lin >> 2, seg = lin & 3;
        size_t src = ((size_t)bx * 512 + mt * 128 + row) * 32 + seg * 8;
        st128(sb + SQH + row * 80 + seg * 16, *(const uint4*)(g_qh + src));
        st128(sb + SQL + row * 80 + seg * 16, *(const uint4*)(g_ql + src));
    }
    CPW0();
    __syncthreads();

    uint32_t aoff = (uint32_t)(((lane & 7) + ((lane >> 3) & 1) * 8) * 80 + (lane >> 4) * 16);
    uint32_t boff = (uint32_t)(((lane & 7) + (lane >> 4) * 8) * 80 + ((lane >> 3) & 1) * 16);
    uint32_t vboff = (uint32_t)(((lane & 7) + (lane >> 4) * 8) * 144 + ((lane >> 3) & 1) * 16);
    uint32_t qh[2][4], ql[2][4];
#pragma unroll
    for (int ks = 0; ks < 2; ks++) {
        ldmx4(qh[ks], sb + SQH + (uint32_t)(wid * 16) * 80 + aoff + ks * 32);
        ldmx4(ql[ks], sb + SQL + (uint32_t)(wid * 16) * 80 + aoff + ks * 32);
    }

    float oacc[4][4];
#pragma unroll
    for (int a = 0; a < 4; a++)
#pragma unroll
        for (int b = 0; b < 4; b++) oacc[a][b] = 0.f;
    float rs0 = 0.f, rs1 = 0.f;
    int quad = lane >> 2, tg = lane & 3;
    int ib = mt * 8 + wid;
    const float* bf = g_bfrag + ((((size_t)cfg * 8 + h) * 32 + ib) * 64) * 128;

#pragma unroll 1
    for (int jt = 0; jt < 8; jt++) {
        if (jt < 7) {
            uint32_t B2 = sb + SBUF + (uint32_t)((jt + 1) & 1) * BSTR;
            CPA16(B2 + KH + kdst, kga + (size_t)(jt + 1) * 4096);
            CPA16(B2 + KL + kdst, kgb + (size_t)(jt + 1) * 4096);
            CPA16(B2 + VTH + vdst, vga + (size_t)(jt + 1) * 128);
            CPA16(B2 + VTL + vdst, vgb + (size_t)(jt + 1) * 128);
            CPC();
        }
        uint32_t B = sb + SBUF + (uint32_t)(jt & 1) * BSTR;

        float sacc[8][4];
#pragma unroll
        for (int a = 0; a < 8; a++)
#pragma unroll
            for (int b = 0; b < 4; b++) sacc[a][b] = 0.f;
#pragma unroll
        for (int ks = 0; ks < 2; ks++)
#pragma unroll
            for (int p = 0; p < 4; p++) {
                uint32_t bh[4], bl[4];
                ldmx4(bh, B + KH + (uint32_t)(p * 16) * 80 + boff + ks * 32);
                ldmx4(bl, B + KL + (uint32_t)(p * 16) * 80 + boff + ks * 32);
#pragma unroll
                for (int n2 = 0; n2 < 2; n2++) {
                    mma16816(sacc[2 * p + n2], qh[ks], &bh[n2 * 2]);
                    mma16816(sacc[2 * p + n2], qh[ks], &bl[n2 * 2]);
                    mma16816(sacc[2 * p + n2], ql[ks], &bh[n2 * 2]);
                }
            }

        uint32_t aPhi[4][4], aPlo[4][4];
#pragma unroll
        for (int nt = 0; nt < 8; nt++) {
            const float2* bp = (const float2*)(bf + (size_t)(jt * 8 + nt) * 128);
            float2 b01 = bp[quad * 4 + tg];
            float2 b23 = bp[32 + quad * 4 + tg];
            float p0 = exp2f(sacc[nt][0] + b01.x);
            float p1 = exp2f(sacc[nt][1] + b01.y);
            float p2 = exp2f(sacc[nt][2] + b23.x);
            float p3 = exp2f(sacc[nt][3] + b23.y);
            rs0 += p0 + p1;
            rs1 += p2 + p3;
            int kt = nt >> 1, o = (nt & 1) * 2;
            split2(p0, p1, aPhi[kt][o], aPlo[kt][o]);
            split2(p2, p3, aPhi[kt][o + 1], aPlo[kt][o + 1]);
        }

#pragma unroll
        for (int kt = 0; kt < 4; kt++)
#pragma unroll
            for (int np = 0; np < 2; np++) {
                uint32_t vh[4], vl[4];
                ldmx4(vh, B + VTH + (uint32_t)(np * 16) * 144 + vboff + kt * 32);
                ldmx4(vl, B + VTL + (uint32_t)(np * 16) * 144 + vboff + kt * 32);
#pragma unroll
                for (int n2 = 0; n2 < 2; n2++) {
                    mma16816(oacc[np * 2 + n2], aPhi[kt], &vh[n2 * 2]);
                    mma16816(oacc[np * 2 + n2], aPhi[kt], &vl[n2 * 2]);
                    mma16816(oacc[np * 2 + n2], aPlo[kt], &vh[n2 * 2]);
                }
            }

        if (jt < 7) {
            CPW0();
            __syncthreads();
        }
    }

    rs0 += __shfl_xor_sync(0xFFFFFFFF, rs0, 1);
    rs0 += __shfl_xor_sync(0xFFFFFFFF, rs0, 2);
    rs1 += __shfl_xor_sync(0xFFFFFFFF, rs1, 1);
    rs1 += __shfl_xor_sync(0xFFFFFFFF, rs1, 2);
    float inv0 = 1.f / rs0, inv1 = 1.f / rs1;
    int qtok = mt * 128 + wid * 16 + quad;
    float* ob = g_att + (size_t)w * 512 * 256 + h * 32;
#pragma unroll
    for (int nt = 0; nt < 4; nt++) {
        float2 o0, o1;
        o0.x = oacc[nt][0] * inv0; o0.y = oacc[nt][1] * inv0;
        o1.x = oacc[nt][2] * inv1; o1.y = oacc[nt][3] * inv1;
        *(float2*)(ob + (size_t)qtok * 256 + nt * 8 + tg * 2) = o0;
        *(float2*)(ob + (size_t)(qtok + 8) * 256 + nt * 8 + tg * 2) = o1;
    }
}

extern "C" void kernel_launch(void* const* d_in, const int* in_sizes, int n_in,
                              void* d_out, int out_size) {
    const float* x      = (const float*)d_in[0];
    const float* qkv_w  = (const float*)d_in[1];
    const float* qkv_b  = (const float*)d_in[2];
    const float* proj_w = (const float*)d_in[3];
    const float* proj_b = (const float*)d_in[4];
    const float* rpb    = (const float*)d_in[5];
    float* out = (float*)d_out;

    cudaFuncSetAttribute(hmma_gemm_kernel, cudaFuncAttributeMaxDynamicSharedMemorySize, 73728);
    cudaFuncSetAttribute(attn_mma_kernel, cudaFuncAttributeMaxDynamicSharedMemorySize, 59392);

    prep_tok_kernel<<<128, 256>>>();
    prep_bias_kernel<<<4096, 512>>>(rpb);
    conv_w_kernel<<<768, 32>>>(qkv_w);
    conv_a_kernel<<<4096, 256>>>(x, 1);
    hmma_gemm_kernel<<<dim3(256, 6), 256, 73728>>>(qkv_b, nullptr, 0);
    attn_mma_kernel<<<2048, 256, 59392>>>();
    conv_w_kernel<<<256, 32>>>(proj_w);
    conv_a_kernel<<<4096, 256>>>(x, 0);
    hmma_gemm_kernel<<<dim3(256, 2), 256, 73728>>>(proj_b, out, 1);
}

// round 10
// speedup vs baseline: 3.0973x; 1.0451x over previous
#include <cuda_runtime.h>
#include <cuda_bf16.h>
#include <math.h>
#include <stdint.h>

#define NWIN 64
#define NTOK 512
#define NHEAD 8
#define HDIM 32
#define CDIM 256
#define KCAT 768
#define MTOT 32768

#define LOG2E 1.4426950408889634f
#define QSCALE (0.17677669529663687f * 1.4426950408889634f)

__device__ __nv_bfloat16 g_qh[(size_t)512 * 512 * 32];
__device__ __nv_bfloat16 g_ql[(size_t)512 * 512 * 32];
__device__ __nv_bfloat16 g_kh[(size_t)512 * 512 * 32];
__device__ __nv_bfloat16 g_kl[(size_t)512 * 512 * 32];
__device__ __nv_bfloat16 g_vth[(size_t)512 * 32 * 512];
__device__ __nv_bfloat16 g_vtl[(size_t)512 * 32 * 512];
__device__ __nv_bfloat16 g_bfrag[(size_t)8 * 8 * 32 * 64 * 128];
__device__ int   g_tokoff[NWIN * NTOK];
__device__ __nv_bfloat16 g_acat[(size_t)MTOT * KCAT];
__device__ __nv_bfloat16 g_bcat[(size_t)768 * KCAT];

__device__ __forceinline__ uint32_t smem_u32(const void* p) {
    uint32_t a;
    asm("{ .reg .u64 t; cvta.to.shared.u64 t, %1; cvt.u32.u64 %0, t; }" : "=r"(a) : "l"(p));
    return a;
}
__device__ __forceinline__ void ldmx4(uint32_t* r, uint32_t addr) {
    asm volatile("ldmatrix.sync.aligned.m8n8.x4.shared.b16 {%0,%1,%2,%3}, [%4];"
                 : "=r"(r[0]), "=r"(r[1]), "=r"(r[2]), "=r"(r[3]) : "r"(addr));
}
__device__ __forceinline__ void st128(uint32_t addr, uint4 v) {
    asm volatile("st.shared.v4.b32 [%0], {%1,%2,%3,%4};"
                 :: "r"(addr), "r"(v.x), "r"(v.y), "r"(v.z), "r"(v.w) : "memory");
}
__device__ __forceinline__ void mma16816(float* c, const uint32_t* a, const uint32_t* b) {
    asm volatile("mma.sync.aligned.m16n8k16.row.col.f32.bf16.bf16.f32 "
                 "{%0,%1,%2,%3}, {%4,%5,%6,%7}, {%8,%9}, {%0,%1,%2,%3};"
                 : "+f"(c[0]), "+f"(c[1]), "+f"(c[2]), "+f"(c[3])
                 : "r"(a[0]), "r"(a[1]), "r"(a[2]), "r"(a[3]), "r"(b[0]), "r"(b[1]));
}
__device__ __forceinline__ void split2(float f0, float f1, uint32_t& hi, uint32_t& lo) {
    __nv_bfloat16 h0 = __float2bfloat16(f0), h1 = __float2bfloat16(f1);
    __nv_bfloat16 l0 = __float2bfloat16(f0 - __bfloat162float(h0));
    __nv_bfloat16 l1 = __float2bfloat16(f1 - __bfloat162float(h1));
    uint16_t uh0 = *(uint16_t*)&h0, uh1 = *(uint16_t*)&h1;
    uint16_t ul0 = *(uint16_t*)&l0, ul1 = *(uint16_t*)&l1;
    hi = (uint32_t)uh0 | ((uint32_t)uh1 << 16);
    lo = (uint32_t)ul0 | ((uint32_t)ul1 << 16);
}
#define CPA16(dst, src) \
    asm volatile("cp.async.cg.shared.global [%0], [%1], 16;" :: "r"(dst), "l"(src) : "memory")
#define CPC() asm volatile("cp.async.commit_group;" ::: "memory")
#define CPW0() asm volatile("cp.async.wait_group 0;" ::: "memory")

// ---------------------------------------------------------------------------
__global__ void prep_tok_kernel() {
    int gid = blockIdx.x * 256 + threadIdx.x;
    int w = gid >> 9, n = gid & 511;
    int wh = w >> 4, ww = (w >> 2) & 3, wd = w & 3;
    int ih = n >> 6, iw = (n >> 3) & 7, id = n & 7;
    int gh = (wh * 8 + ih + 4) & 31;
    int gw = (ww * 8 + iw + 4) & 31;
    int gd = (wd * 8 + id + 4) & 31;
    g_tokoff[gid] = ((gh * 32 + gw) * 32 + gd) * 256;
}

// ---------------------------------------------------------------------------
// prep_bias: bf16 output, D-frag layout.
// ---------------------------------------------------------------------------
__global__ void __launch_bounds__(512) prep_bias_kernel(const float* __restrict__ rpb) {
    int cfg = blockIdx.x >> 9, i = blockIdx.x & 511;
    int h = threadIdx.x >> 6, jb = threadIdx.x & 63;
    int ch = (cfg >> 2) & 1, cw = (cfg >> 1) & 1, cd = cfg & 1;
    int i0 = i >> 6, i1 = (i >> 3) & 7, i2 = i & 7;
    int ri = (ch ? (i0 < 4 ? 1 : 2) : 0) * 9 + (cw ? (i1 < 4 ? 1 : 2) : 0) * 3
           + (cd ? (i2 < 4 ? 1 : 2) : 0);
    int ib = i >> 4, half = (i & 15) >> 3, row = i & 7;
    int j0 = jb >> 3, j1 = jb & 7;
    int rjb = (ch ? (j0 < 4 ? 1 : 2) : 0) * 9 + (cw ? (j1 < 4 ? 1 : 2) : 0) * 3;
    int idxb = (i0 - j0 + 7) * 225 + (i1 - j1 + 7) * 15;
    union { __nv_bfloat16 h8[8]; uint4 u; } O;
#pragma unroll
    for (int j2 = 0; j2 < 8; j2++) {
        int rj = rjb + (cd ? (j2 < 4 ? 1 : 2) : 0);
        int idx = idxb + (i2 - j2 + 7);
        float m = (ri == rj) ? 0.f : -100.f;
        O.h8[j2] = __float2bfloat16((rpb[idx * 8 + h] + m) * LOG2E);
    }
    size_t base = (((((size_t)cfg * 8 + h) * 32 + ib) * 64 + jb) * 128) + half * 64 + row * 8;
    *(uint4*)(g_bfrag + base) = O.u;
}

// ---------------------------------------------------------------------------
// conv_a (x gather) / conv_w: fp32 -> bf16 3-term split.
// ---------------------------------------------------------------------------
__global__ void conv_a_kernel(const float* __restrict__ src) {
    int row = blockIdx.x * 8 + (threadIdx.x >> 5);
    int c8 = (threadIdx.x & 31) * 8;
    const float* sp = src + g_tokoff[row];
    float4 v0 = *(const float4*)(sp + c8);
    float4 v1 = *(const float4*)(sp + c8 + 4);
    float f[8] = {v0.x, v0.y, v0.z, v0.w, v1.x, v1.y, v1.z, v1.w};
    union { __nv_bfloat16 h[8]; uint4 u; } H, L;
#pragma unroll
    for (int i = 0; i < 8; i++) {
        H.h[i] = __float2bfloat16(f[i]);
        L.h[i] = __float2bfloat16(f[i] - __bfloat162float(H.h[i]));
    }
    __nv_bfloat16* dst = g_acat + (size_t)row * KCAT;
    *(uint4*)(dst + c8)       = H.u;
    *(uint4*)(dst + 256 + c8) = H.u;
    *(uint4*)(dst + 512 + c8) = L.u;
}

__global__ void conv_w_kernel(const float* __restrict__ W) {
    int row = blockIdx.x;
    int c8 = threadIdx.x * 8;
    const float* sp = W + (size_t)row * 256 + c8;
    float4 v0 = *(const float4*)(sp);
    float4 v1 = *(const float4*)(sp + 4);
    float f[8] = {v0.x, v0.y, v0.z, v0.w, v1.x, v1.y, v1.z, v1.w};
    union { __nv_bfloat16 h[8]; uint4 u; } H, L;
#pragma unroll
    for (int i = 0; i < 8; i++) {
        H.h[i] = __float2bfloat16(f[i]);
        L.h[i] = __float2bfloat16(f[i] - __bfloat162float(H.h[i]));
    }
    __nv_bfloat16* dst = g_bcat + (size_t)row * KCAT;
    *(uint4*)(dst + c8)       = H.u;
    *(uint4*)(dst + 256 + c8) = L.u;
    *(uint4*)(dst + 512 + c8) = H.u;
}

// ---------------------------------------------------------------------------
// HMMA GEMM (unchanged from R8).
// ---------------------------------------------------------------------------
__global__ void __launch_bounds__(256, 2) hmma_gemm_kernel(const float* __restrict__ bias,
                                                           float* __restrict__ out, int mode) {
    extern __shared__ __align__(16) char smem[];
    uint32_t sbase = smem_u32(smem);
    int tid = threadIdx.x;
    int lane = tid & 31, wid = tid >> 5;
    int wm = wid & 3, wn = wid >> 2;
    int m0 = blockIdx.x * 128, n0 = blockIdx.y * 128;

    int lr = tid >> 1, lh = tid & 1;
    const char* Agb = (const char*)g_acat + (size_t)(m0 + lr) * 1536 + lh * 64;
    const char* Bgb = (const char*)g_bcat + (size_t)(n0 + lr) * 1536 + lh * 64;
    uint32_t stoff = (uint32_t)(lr * 144 + lh * 64);

    uint32_t aoff = (uint32_t)((((lane & 7) + ((lane >> 3) & 1) * 8) * 144) + (lane >> 4) * 16);
    uint32_t boff = (uint32_t)((((lane & 7) + (lane >> 4) * 8) * 144) + ((lane >> 3) & 1) * 16);

    float acc[2][8][4];
#pragma unroll
    for (int a = 0; a < 2; a++)
#pragma unroll
        for (int b = 0; b < 8; b++)
#pragma unroll
            for (int c = 0; c < 4; c++) acc[a][b][c] = 0.f;

#pragma unroll
    for (int i = 0; i < 4; i++) {
        CPA16(sbase + stoff + i * 16, Agb + i * 16);
        CPA16(sbase + 36864u + stoff + i * 16, Bgb + i * 16);
    }
    CPC();
    CPW0();
    __syncthreads();

#pragma unroll 1
    for (int c = 0; c < 12; c++) {
        if (c < 11) {
            uint32_t nb = (uint32_t)((c + 1) & 1);
            const char* As = Agb + (size_t)(c + 1) * 128;
            const char* Bs = Bgb + (size_t)(c + 1) * 128;
#pragma unroll
            for (int i = 0; i < 4; i++) {
                CPA16(sbase + nb * 18432u + stoff + i * 16, As + i * 16);
                CPA16(sbase + 36864u + nb * 18432u + stoff + i * 16, Bs + i * 16);
            }
            CPC();
        }
        uint32_t Ab = sbase + (uint32_t)(c & 1) * 18432u;
        uint32_t Bb = sbase + 36864u + (uint32_t)(c & 1) * 18432u;
        uint32_t Abw = Ab + (uint32_t)(wm * 32) * 144u + aoff;
        uint32_t Bbw = Bb + (uint32_t)(wn * 64) * 144u + boff;
#pragma unroll
        for (int ks = 0; ks < 4; ks++) {
            uint32_t afr[2][4];
#pragma unroll
            for (int mt = 0; mt < 2; mt++)
                ldmx4(afr[mt], Abw + (uint32_t)(mt * 16) * 144u + ks * 32u);
            uint32_t bfr[8][2];
#pragma unroll
            for (int p = 0; p < 4; p++) {
                uint32_t t4[4];
                ldmx4(t4, Bbw + (uint32_t)(p * 16) * 144u + ks * 32u);
                bfr[2 * p][0] = t4[0]; bfr[2 * p][1] = t4[1];
                bfr[2 * p + 1][0] = t4[2]; bfr[2 * p + 1][1] = t4[3];
            }
#pragma unroll
            for (int mt = 0; mt < 2; mt++)
#pragma unroll
                for (int nt = 0; nt < 8; nt++)
                    mma16816(acc[mt][nt], afr[mt], bfr[nt]);
        }
        if (c < 11) {
            CPW0();
            __syncthreads();
        }
    }

    int quad = lane >> 2, tg = lane & 3;
#pragma unroll
    for (int mt = 0; mt < 2; mt++) {
        int rbase = m0 + wm * 32 + mt * 16 + quad;
#pragma unroll
        for (int nt = 0; nt < 8; nt++) {
            int col = n0 + wn * 64 + nt * 8 + tg * 2;
            float2 bb = *(const float2*)(bias + col);
            if (mode == 0) {
                int sec = n0 >> 8;
                float sc = (sec == 0) ? QSCALE : 1.0f;
                int head = (col & 255) >> 5, dd = col & 31;
#pragma unroll
                for (int hf = 0; hf < 2; hf++) {
                    int rr = rbase + hf * 8;
                    int w = rr >> 9, nn = rr & 511;
                    size_t bxi = (size_t)(w * 8 + head);
                    float f0 = (acc[mt][nt][hf * 2 + 0] + bb.x) * sc;
                    float f1 = (acc[mt][nt][hf * 2 + 1] + bb.y) * sc;
                    uint32_t hi, lo;
                    split2(f0, f1, hi, lo);
                    if (sec <= 1) {
                        __nv_bfloat16* dh = (sec == 0 ? g_qh : g_kh) + (bxi * 512 + nn) * 32 + dd;
                        __nv_bfloat16* dl = (sec == 0 ? g_ql : g_kl) + (bxi * 512 + nn) * 32 + dd;
                        *(uint32_t*)dh = hi;
                        *(uint32_t*)dl = lo;
                    } else {
                        g_vth[(bxi * 32 + dd) * 512 + nn]     = *(__nv_bfloat16*)&hi;
                        g_vth[(bxi * 32 + dd + 1) * 512 + nn] = ((__nv_bfloat162*)&hi)->y;
                        g_vtl[(bxi * 32 + dd) * 512 + nn]     = *(__nv_bfloat16*)&lo;
                        g_vtl[(bxi * 32 + dd + 1) * 512 + nn] = ((__nv_bfloat162*)&lo)->y;
                    }
                }
            } else {
#pragma unroll
                for (int hf = 0; hf < 2; hf++) {
                    int rr = rbase + hf * 8;
                    int off = g_tokoff[rr] + col;
                    float2 o;
                    o.x = acc[mt][nt][hf * 2 + 0] + bb.x;
                    o.y = acc[mt][nt][hf * 2 + 1] + bb.y;
                    *(float2*)(out + off) = o;
                }
            }
        }
    }
}

// ---------------------------------------------------------------------------
// HMMA attention: split-P PV restored (Phi*Vh + Phi*Vl + Plo*Vh), bf16 bias
// frags, fused proj-A epilogue into g_acat.
// ---------------------------------------------------------------------------
__global__ void __launch_bounds__(256, 2) attn_mma_kernel() {
    extern __shared__ __align__(16) char sm[];
    uint32_t sb = smem_u32(sm);
    const int tid = threadIdx.x, lane = tid & 31, wid = tid >> 5;
    int bx = blockIdx.x >> 2, mt = blockIdx.x & 3;
    int w = bx >> 3, h = bx & 7;
    int cfg = (((w >> 4) == 3) ? 4 : 0) | ((((w >> 2) & 3) == 3) ? 2 : 0) | (((w & 3) == 3) ? 1 : 0);

    const uint32_t SQH = 0, SQL = 10240, SBUF = 20480, BSTR = 19456;
    const uint32_t KH = 0, KL = 5120, VTH = 10240, VTL = 14848;

    int row_k = tid >> 2, seg_k = tid & 3;
    int row_v = tid >> 3, seg_v = tid & 7;
    const char* kga = (const char*)(g_kh + (size_t)bx * 512 * 32 + (size_t)row_k * 32 + seg_k * 8);
    const char* kgb = (const char*)(g_kl + (size_t)bx * 512 * 32 + (size_t)row_k * 32 + seg_k * 8);
    const char* vga = (const char*)(g_vth + (size_t)bx * 32 * 512 + (size_t)row_v * 512 + seg_v * 8);
    const char* vgb = (const char*)(g_vtl + (size_t)bx * 32 * 512 + (size_t)row_v * 512 + seg_v * 8);
    uint32_t kdst = row_k * 80 + seg_k * 16;
    uint32_t vdst = row_v * 144 + seg_v * 16;

    CPA16(sb + SBUF + KH + kdst, kga);
    CPA16(sb + SBUF + KL + kdst, kgb);
    CPA16(sb + SBUF + VTH + vdst, vga);
    CPA16(sb + SBUF + VTL + vdst, vgb);
    CPC();

#pragma unroll
    for (int u = 0; u < 2; u++) {
        int lin = tid + u * 256;
        int row = lin >> 2, seg = lin & 3;
        size_t src = ((size_t)bx * 512 + mt * 128 + row) * 32 + seg * 8;
        st128(sb + SQH + row * 80 + seg * 16, *(const uint4*)(g_qh + src));
        st128(sb + SQL + row * 80 + seg * 16, *(const uint4*)(g_ql + src));
    }
    CPW0();
    __syncthreads();

    uint32_t aoff = (uint32_t)(((lane & 7) + ((lane >> 3) & 1) * 8) * 80 + (lane >> 4) * 16);
    uint32_t boff = (uint32_t)(((lane & 7) + (lane >> 4) * 8) * 80 + ((lane >> 3) & 1) * 16);
    uint32_t vboff = (uint32_t)(((lane & 7) + (lane >> 4) * 8) * 144 + ((lane >> 3) & 1) * 16);
    uint32_t qh[2][4], ql[2][4];
#pragma unroll
    for (int ks = 0; ks < 2; ks++) {
        ldmx4(qh[ks], sb + SQH + (uint32_t)(wid * 16) * 80 + aoff + ks * 32);
        ldmx4(ql[ks], sb + SQL + (uint32_t)(wid * 16) * 80 + aoff + ks * 32);
    }

    float oacc[4][4];
#pragma unroll
    for (int a = 0; a < 4; a++)
#pragma unroll
        for (int b = 0; b < 4; b++) oacc[a][b] = 0.f;
    float rs0 = 0.f, rs1 = 0.f;
    int quad = lane >> 2, tg = lane & 3;
    int ib = mt * 8 + wid;
    const __nv_bfloat16* bf = g_bfrag + ((((size_t)cfg * 8 + h) * 32 + ib) * 64) * 128;

#pragma unroll 1
    for (int jt = 0; jt < 8; jt++) {
        if (jt < 7) {
            uint32_t B2 = sb + SBUF + (uint32_t)((jt + 1) & 1) * BSTR;
            CPA16(B2 + KH + kdst, kga + (size_t)(jt + 1) * 4096);
            CPA16(B2 + KL + kdst, kgb + (size_t)(jt + 1) * 4096);
            CPA16(B2 + VTH + vdst, vga + (size_t)(jt + 1) * 128);
            CPA16(B2 + VTL + vdst, vgb + (size_t)(jt + 1) * 128);
            CPC();
        }
        uint32_t B = sb + SBUF + (uint32_t)(jt & 1) * BSTR;

        float sacc[8][4];
#pragma unroll
        for (int a = 0; a < 8; a++)
#pragma unroll
            for (int b = 0; b < 4; b++) sacc[a][b] = 0.f;
#pragma unroll
        for (int ks = 0; ks < 2; ks++)
#pragma unroll
            for (int p = 0; p < 4; p++) {
                uint32_t bh[4], bl[4];
                ldmx4(bh, B + KH + (uint32_t)(p * 16) * 80 + boff + ks * 32);
                ldmx4(bl, B + KL + (uint32_t)(p * 16) * 80 + boff + ks * 32);
#pragma unroll
                for (int n2 = 0; n2 < 2; n2++) {
                    mma16816(sacc[2 * p + n2], qh[ks], &bh[n2 * 2]);
                    mma16816(sacc[2 * p + n2], qh[ks], &bl[n2 * 2]);
                    mma16816(sacc[2 * p + n2], ql[ks], &bh[n2 * 2]);
                }
            }

        uint32_t aPhi[4][4], aPlo[4][4];
#pragma unroll
        for (int nt = 0; nt < 8; nt++) {
            const uint32_t* bp = (const uint32_t*)(bf + (size_t)(jt * 8 + nt) * 128);
            __nv_bfloat162 bb01 = *(const __nv_bfloat162*)&bp[quad * 4 + tg];
            __nv_bfloat162 bb23 = *(const __nv_bfloat162*)&bp[32 + quad * 4 + tg];
            float2 b01 = __bfloat1622float2(bb01);
            float2 b23 = __bfloat1622float2(bb23);
            float p0 = exp2f(sacc[nt][0] + b01.x);
            float p1 = exp2f(sacc[nt][1] + b01.y);
            float p2 = exp2f(sacc[nt][2] + b23.x);
            float p3 = exp2f(sacc[nt][3] + b23.y);
            rs0 += p0 + p1;
            rs1 += p2 + p3;
            int kt = nt >> 1, o = (nt & 1) * 2;
            split2(p0, p1, aPhi[kt][o], aPlo[kt][o]);
            split2(p2, p3, aPhi[kt][o + 1], aPlo[kt][o + 1]);
        }

#pragma unroll
        for (int kt = 0; kt < 4; kt++)
#pragma unroll
            for (int np = 0; np < 2; np++) {
                uint32_t vh[4], vl[4];
                ldmx4(vh, B + VTH + (uint32_t)(np * 16) * 144 + vboff + kt * 32);
                ldmx4(vl, B + VTL + (uint32_t)(np * 16) * 144 + vboff + kt * 32);
#pragma unroll
                for (int n2 = 0; n2 < 2; n2++) {
                    mma16816(oacc[np * 2 + n2], aPhi[kt], &vh[n2 * 2]);
                    mma16816(oacc[np * 2 + n2], aPhi[kt], &vl[n2 * 2]);
                    mma16816(oacc[np * 2 + n2], aPlo[kt], &vh[n2 * 2]);
                }
            }

        if (jt < 7) {
            CPW0();
            __syncthreads();
        }
    }

    rs0 += __shfl_xor_sync(0xFFFFFFFF, rs0, 1);
    rs0 += __shfl_xor_sync(0xFFFFFFFF, rs0, 2);
    rs1 += __shfl_xor_sync(0xFFFFFFFF, rs1, 1);
    rs1 += __shfl_xor_sync(0xFFFFFFFF, rs1, 2);
    float inv0 = 1.f / rs0, inv1 = 1.f / rs1;
    int qtok = mt * 128 + wid * 16 + quad;
    int t0 = w * 512 + qtok, t1 = t0 + 8;
#pragma unroll
    for (int nt = 0; nt < 4; nt++) {
        int c = h * 32 + nt * 8 + tg * 2;
        uint32_t hi, lo;
        split2(oacc[nt][0] * inv0, oacc[nt][1] * inv0, hi, lo);
        __nv_bfloat16* d0 = g_acat + (size_t)t0 * KCAT + c;
        *(uint32_t*)d0         = hi;
        *(uint32_t*)(d0 + 256) = hi;
        *(uint32_t*)(d0 + 512) = lo;
        split2(oacc[nt][2] * inv1, oacc[nt][3] * inv1, hi, lo);
        __nv_bfloat16* d1 = g_acat + (size_t)t1 * KCAT + c;
        *(uint32_t*)d1         = hi;
        *(uint32_t*)(d1 + 256) = hi;
        *(uint32_t*)(d1 + 512) = lo;
    }
}

extern "C" void kernel_launch(void* const* d_in, const int* in_sizes, int n_in,
                              void* d_out, int out_size) {
    const float* x      = (const float*)d_in[0];
    const float* qkv_w  = (const float*)d_in[1];
    const float* qkv_b  = (const float*)d_in[2];
    const float* proj_w = (const float*)d_in[3];
    const float* proj_b = (const float*)d_in[4];
    const float* rpb    = (const float*)d_in[5];
    float* out = (float*)d_out;

    cudaFuncSetAttribute(hmma_gemm_kernel, cudaFuncAttributeMaxDynamicSharedMemorySize, 73728);
    cudaFuncSetAttribute(attn_mma_kernel, cudaFuncAttributeMaxDynamicSharedMemorySize, 59392);

    prep_tok_kernel<<<128, 256>>>();
    prep_bias_kernel<<<4096, 512>>>(rpb);
    conv_w_kernel<<<768, 32>>>(qkv_w);
    conv_a_kernel<<<4096, 256>>>(x);
    hmma_gemm_kernel<<<dim3(256, 6), 256, 73728>>>(qkv_b, nullptr, 0);
    conv_w_kernel<<<256, 32>>>(proj_w);
    attn_mma_kernel<<<2048, 256, 59392>>>();
    hmma_gemm_kernel<<<dim3(256, 2), 256, 73728>>>(proj_b, out, 1);
}